// round 1
// baseline (speedup 1.0000x reference)
#include <cuda_runtime.h>
#include <cstdint>
#include <math.h>

// Problem constants
#define V_   32000
#define C_   768
#define T_   1024
#define H_   12
#define HS_  64
#define FF_  9216
#define NB_  3
#define B_   4
#define M_   (B_ * T_)          // 4096 rows
#define EPS_ 1e-5f
#define SCALE_ 0.03608439182435161f   // 768^-0.5 (reference uses n_embd, not head_size)

// ----------------------------------------------------------------------------
// Scratch (static device globals; no allocation at runtime)
// ----------------------------------------------------------------------------
__device__ float g_x[M_ * C_];
__device__ float g_h[M_ * C_];
__device__ float g_qkv[M_ * 3 * C_];        // [row][ q(768) | k(768) | v(768) ]
__device__ float g_o[M_ * C_];
__device__ float g_wqkv[C_ * 3 * C_];       // packed [768, 2304]
__device__ float g_ff[(size_t)M_ * FF_];    // 151 MB
__device__ float g_rowloss[M_];

// ----------------------------------------------------------------------------
// Embedding: x[b,t,c] = tok_emb[src[b,t], c] + pos_emb[t, c]
// ----------------------------------------------------------------------------
__global__ void embed_k(const float* __restrict__ tok, const float* __restrict__ pos,
                        const int* __restrict__ src) {
    int idx = blockIdx.x * blockDim.x + threadIdx.x;   // M_*C_ threads
    int row = idx / C_;
    int c   = idx - row * C_;
    int t   = row % T_;
    g_x[idx] = tok[(size_t)src[row] * C_ + c] + pos[t * C_ + c];
}

// ----------------------------------------------------------------------------
// LayerNorm: one block (256 threads) per row
// ----------------------------------------------------------------------------
__global__ void ln_k(const float* __restrict__ in, float* __restrict__ out,
                     const float* __restrict__ g, const float* __restrict__ b) {
    __shared__ float red[256];
    int row = blockIdx.x;
    int tid = threadIdx.x;
    const float* x = in + (size_t)row * C_;

    float s = 0.f, s2 = 0.f;
    for (int c = tid; c < C_; c += 256) { float v = x[c]; s += v; s2 += v * v; }

    red[tid] = s; __syncthreads();
    for (int st = 128; st > 0; st >>= 1) { if (tid < st) red[tid] += red[tid + st]; __syncthreads(); }
    float mean = red[0] * (1.f / C_);
    __syncthreads();
    red[tid] = s2; __syncthreads();
    for (int st = 128; st > 0; st >>= 1) { if (tid < st) red[tid] += red[tid + st]; __syncthreads(); }
    float var = red[0] * (1.f / C_) - mean * mean;
    float inv = rsqrtf(var + EPS_);

    for (int c = tid; c < C_; c += 256)
        out[(size_t)row * C_ + c] = (x[c] - mean) * inv * g[c] + b[c];
}

// ----------------------------------------------------------------------------
// Pack wq/wk/wv (each [H, C, HS]) into g_wqkv [C, 3C] row-major.
// column j in [0,768): q head h=j/64, d=j%64; [768,1536): k; [1536,2304): v
// ----------------------------------------------------------------------------
__global__ void pack_qkv_k(const float* __restrict__ wq, const float* __restrict__ wk,
                           const float* __restrict__ wv) {
    int idx = blockIdx.x * blockDim.x + threadIdx.x;   // C_*3*C_
    if (idx >= C_ * 3 * C_) return;
    int c   = idx / (3 * C_);
    int col = idx - c * (3 * C_);
    const float* w = (col < C_) ? wq : (col < 2 * C_ ? wk : wv);
    int j = col % C_;
    int h = j / HS_, d = j % HS_;
    g_wqkv[idx] = w[((size_t)h * C_ + c) * HS_ + d];
}

// ----------------------------------------------------------------------------
// Tiled fp32 GEMM: C[M,N] (+)= A[M,K] @ B[K,N] + bias, optional ReLU.
// BM=BN=64, BK=16, 256 threads, 4x4 per thread. All dims divisible by tiles.
// ----------------------------------------------------------------------------
template<bool ADD, bool RELU>
__global__ void gemm_k(const float* __restrict__ A, const float* __restrict__ B,
                       float* __restrict__ Cc, const float* __restrict__ bias,
                       int Kdim, int Ndim) {
    __shared__ float As[16][65];
    __shared__ float Bs[16][68];

    int tid  = threadIdx.x;
    int brow = blockIdx.y * 64;
    int bcol = blockIdx.x * 64;

    int arow = tid >> 2;            // 0..63
    int acol = (tid & 3) * 4;       // 0,4,8,12
    int brw  = tid >> 4;            // 0..15
    int bcl  = (tid & 15) * 4;      // 0..60

    int ty = tid >> 4, tx = tid & 15;
    float acc[4][4] = {};

    const float* Ap = A + (size_t)(brow + arow) * Kdim + acol;
    const float* Bp = B + (size_t)brw * Ndim + bcol + bcl;

    for (int k0 = 0; k0 < Kdim; k0 += 16) {
        float4 av = *(const float4*)(Ap + k0);
        As[acol + 0][arow] = av.x;
        As[acol + 1][arow] = av.y;
        As[acol + 2][arow] = av.z;
        As[acol + 3][arow] = av.w;
        float4 bv = *(const float4*)(Bp + (size_t)k0 * Ndim);
        *(float4*)&Bs[brw][bcl] = bv;
        __syncthreads();
#pragma unroll
        for (int k = 0; k < 16; k++) {
            float a0 = As[k][ty * 4 + 0], a1 = As[k][ty * 4 + 1];
            float a2 = As[k][ty * 4 + 2], a3 = As[k][ty * 4 + 3];
            float b0 = Bs[k][tx * 4 + 0], b1 = Bs[k][tx * 4 + 1];
            float b2 = Bs[k][tx * 4 + 2], b3 = Bs[k][tx * 4 + 3];
            acc[0][0] += a0 * b0; acc[0][1] += a0 * b1; acc[0][2] += a0 * b2; acc[0][3] += a0 * b3;
            acc[1][0] += a1 * b0; acc[1][1] += a1 * b1; acc[1][2] += a1 * b2; acc[1][3] += a1 * b3;
            acc[2][0] += a2 * b0; acc[2][1] += a2 * b1; acc[2][2] += a2 * b2; acc[2][3] += a2 * b3;
            acc[3][0] += a3 * b0; acc[3][1] += a3 * b1; acc[3][2] += a3 * b2; acc[3][3] += a3 * b3;
        }
        __syncthreads();
    }

#pragma unroll
    for (int i = 0; i < 4; i++) {
        int r = brow + ty * 4 + i;
#pragma unroll
        for (int j = 0; j < 4; j++) {
            int cidx = bcol + tx * 4 + j;
            float v = acc[i][j];
            if (bias) v += bias[cidx];
            size_t off = (size_t)r * Ndim + cidx;
            if (ADD) v += Cc[off];
            if (RELU) v = fmaxf(v, 0.f);
            Cc[off] = v;
        }
    }
}

// ----------------------------------------------------------------------------
// Attention: one block (128 threads) per (t, h, b). Causal: only j <= t.
// q/k/v rows live in g_qkv at offsets 0 / 768 / 1536. Output -> g_o (heads concat).
// ----------------------------------------------------------------------------
__global__ void attn_k() {
    __shared__ float sc[T_];
    __shared__ float qs[HS_];
    __shared__ float red[128];
    __shared__ float obuf[2][HS_];

    int t = blockIdx.x, h = blockIdx.y, b = blockIdx.z;
    int tid = threadIdx.x;
    int lane = tid & 31, w = tid >> 5;
    size_t rowbase = (size_t)(b * T_) * (3 * C_);
    int hoff = h * HS_;

    if (tid < HS_) qs[tid] = g_qkv[rowbase + (size_t)t * 3 * C_ + hoff + tid];
    __syncthreads();

    // scores: each warp handles j = w, w+4, ...
    for (int j = w; j <= t; j += 4) {
        const float* kp = &g_qkv[rowbase + (size_t)j * 3 * C_ + C_ + hoff];
        float p = qs[lane] * kp[lane] + qs[lane + 32] * kp[lane + 32];
#pragma unroll
        for (int o = 16; o > 0; o >>= 1) p += __shfl_down_sync(0xffffffffu, p, o);
        if (lane == 0) sc[j] = p * SCALE_;
    }
    __syncthreads();

    // max
    float mx = -3.4e38f;
    for (int j = tid; j <= t; j += 128) mx = fmaxf(mx, sc[j]);
    red[tid] = mx; __syncthreads();
    for (int st = 64; st > 0; st >>= 1) { if (tid < st) red[tid] = fmaxf(red[tid], red[tid + st]); __syncthreads(); }
    mx = red[0]; __syncthreads();

    // exp + sum
    float s = 0.f;
    for (int j = tid; j <= t; j += 128) { float e = __expf(sc[j] - mx); sc[j] = e; s += e; }
    red[tid] = s; __syncthreads();
    for (int st = 64; st > 0; st >>= 1) { if (tid < st) red[tid] += red[tid + st]; __syncthreads(); }
    float inv = 1.f / red[0];
    __syncthreads();

    // output: two groups of 64 threads split the j loop; coalesced v reads
    int g = tid >> 6, d = tid & 63;
    float acc = 0.f;
    for (int j = g; j <= t; j += 2)
        acc += sc[j] * g_qkv[rowbase + (size_t)j * 3 * C_ + 2 * C_ + hoff + d];
    obuf[g][d] = acc;
    __syncthreads();
    if (tid < HS_)
        g_o[(size_t)(b * T_ + t) * C_ + hoff + tid] = (obuf[0][tid] + obuf[1][tid]) * inv;
}

// ----------------------------------------------------------------------------
// Loss: per-row log-softmax NLL, then mean
// ----------------------------------------------------------------------------
__global__ void rowloss_k(const float* __restrict__ logits, const int* __restrict__ tgt) {
    __shared__ float red[256];
    int row = blockIdx.x;
    int tid = threadIdx.x;
    const float* L = logits + (size_t)row * V_;

    float mx = -3.4e38f;
    for (int j = tid; j < V_; j += 256) mx = fmaxf(mx, L[j]);
    red[tid] = mx; __syncthreads();
    for (int st = 128; st > 0; st >>= 1) { if (tid < st) red[tid] = fmaxf(red[tid], red[tid + st]); __syncthreads(); }
    mx = red[0]; __syncthreads();

    float s = 0.f;
    for (int j = tid; j < V_; j += 256) s += __expf(L[j] - mx);
    red[tid] = s; __syncthreads();
    for (int st = 128; st > 0; st >>= 1) { if (tid < st) red[tid] += red[tid + st]; __syncthreads(); }
    if (tid == 0)
        g_rowloss[row] = -(L[tgt[row]] - mx - logf(red[0]));
}

__global__ void finloss_k(float* __restrict__ out) {
    __shared__ float red[256];
    int tid = threadIdx.x;
    float s = 0.f;
    for (int j = tid; j < M_; j += 256) s += g_rowloss[j];
    red[tid] = s; __syncthreads();
    for (int st = 128; st > 0; st >>= 1) { if (tid < st) red[tid] += red[tid + st]; __syncthreads(); }
    if (tid == 0) out[0] = red[0] * (1.f / M_);
}

// ----------------------------------------------------------------------------
// Host driver
// ----------------------------------------------------------------------------
extern "C" void kernel_launch(void* const* d_in, const int* in_sizes, int n_in,
                              void* d_out, int out_size) {
    const float* tok_emb = (const float*)d_in[0];
    const float* pos_emb = (const float*)d_in[1];
    const float* wq      = (const float*)d_in[2];
    const float* wk      = (const float*)d_in[3];
    const float* wv      = (const float*)d_in[4];
    const float* wproj   = (const float*)d_in[5];
    const float* bproj   = (const float*)d_in[6];
    const float* g1      = (const float*)d_in[7];
    const float* b1      = (const float*)d_in[8];
    const float* g2      = (const float*)d_in[9];
    const float* b2      = (const float*)d_in[10];
    const float* wf1     = (const float*)d_in[11];
    const float* bf1     = (const float*)d_in[12];
    const float* wf2     = (const float*)d_in[13];
    const float* bf2     = (const float*)d_in[14];
    const float* gf      = (const float*)d_in[15];
    const float* bf      = (const float*)d_in[16];
    const float* wlm     = (const float*)d_in[17];
    const float* blm     = (const float*)d_in[18];
    const int*   sources = (const int*)d_in[19];
    const int*   targets = (const int*)d_in[20];

    float* out = (float*)d_out;
    const size_t n_logits = (size_t)M_ * V_;

    // resolve device scratch symbols
    float *px, *ph, *pqkv, *po, *pwqkv, *pff;
    cudaGetSymbolAddress((void**)&px,    g_x);
    cudaGetSymbolAddress((void**)&ph,    g_h);
    cudaGetSymbolAddress((void**)&pqkv,  g_qkv);
    cudaGetSymbolAddress((void**)&po,    g_o);
    cudaGetSymbolAddress((void**)&pwqkv, g_wqkv);
    cudaGetSymbolAddress((void**)&pff,   g_ff);

    // 1. embedding
    embed_k<<<(M_ * C_) / 256, 256>>>(tok_emb, pos_emb, sources);

    // 2. transformer blocks
    for (int i = 0; i < NB_; i++) {
        const float* wq_i = wq + (size_t)i * H_ * C_ * HS_;
        const float* wk_i = wk + (size_t)i * H_ * C_ * HS_;
        const float* wv_i = wv + (size_t)i * H_ * C_ * HS_;

        ln_k<<<M_, 256>>>(px, ph, g1 + i * C_, b1 + i * C_);
        pack_qkv_k<<<(C_ * 3 * C_ + 255) / 256, 256>>>(wq_i, wk_i, wv_i);

        // qkv = h @ Wqkv : [4096, 2304]
        gemm_k<false, false><<<dim3((3 * C_) / 64, M_ / 64), 256>>>(ph, pwqkv, pqkv, nullptr, C_, 3 * C_);

        attn_k<<<dim3(T_, H_, B_), 128>>>();

        // x += o @ wproj + bproj
        gemm_k<true, false><<<dim3(C_ / 64, M_ / 64), 256>>>(po, wproj + (size_t)i * C_ * C_, px,
                                                             bproj + i * C_, C_, C_);

        ln_k<<<M_, 256>>>(px, ph, g2 + i * C_, b2 + i * C_);

        // ff = relu(h @ wf1 + bf1)
        gemm_k<false, true><<<dim3(FF_ / 64, M_ / 64), 256>>>(ph, wf1 + (size_t)i * C_ * FF_, pff,
                                                              bf1 + i * FF_, C_, FF_);
        // x += ff @ wf2 + bf2
        gemm_k<true, false><<<dim3(C_ / 64, M_ / 64), 256>>>(pff, wf2 + (size_t)i * FF_ * C_, px,
                                                             bf2 + i * C_, FF_, C_);
    }

    // 3. final LN + LM head -> logits straight into d_out
    ln_k<<<M_, 256>>>(px, ph, gf, bf);
    gemm_k<false, false><<<dim3(V_ / 64, M_ / 64), 256>>>(ph, wlm, out, blm, C_, V_);

    // 4. loss
    rowloss_k<<<M_, 256>>>(out, targets);
    if ((size_t)out_size > n_logits)
        finloss_k<<<1, 256>>>(out + n_logits);
}

// round 2
// speedup vs baseline: 2.2120x; 2.2120x over previous
#include <cuda_runtime.h>
#include <cstdint>
#include <math.h>

// Problem constants
#define V_   32000
#define C_   768
#define T_   1024
#define H_   12
#define HS_  64
#define FF_  9216
#define NB_  3
#define B_   4
#define M_   (B_ * T_)          // 4096 rows
#define EPS_ 1e-5f
#define SCALE_ 0.03608439182435161f   // 768^-0.5

// GEMM tiling
#define BM 128
#define BN 128
#define BK 32
#define AS_STRIDE 36            // 36*4=144B, multiple of 16, bank-conflict-free frags
#define BS_STRIDE 136           // 136*4=544B, multiple of 16, stride mod 32 = 8
#define AS_SZ (BM * AS_STRIDE)  // 4608 floats
#define BS_SZ (BK * BS_STRIDE)  // 4352 floats
#define SMEM_BYTES (2 * (AS_SZ + BS_SZ) * 4)   // 71680

// ----------------------------------------------------------------------------
// Scratch (static device globals)
// ----------------------------------------------------------------------------
__device__ float g_x[M_ * C_];
__device__ float g_h[M_ * C_];
__device__ float g_qkv[M_ * 3 * C_];
__device__ float g_o[M_ * C_];
__device__ float g_wqkv[C_ * 3 * C_];
__device__ float g_ff[(size_t)M_ * FF_];
__device__ float g_rowloss[M_];

// ----------------------------------------------------------------------------
// PTX helpers
// ----------------------------------------------------------------------------
#define CP16(dst, src) asm volatile("cp.async.cg.shared.global [%0], [%1], 16;\n" :: "r"(dst), "l"(src) : "memory")
#define CP_COMMIT() asm volatile("cp.async.commit_group;\n" ::: "memory")

__device__ __forceinline__ uint32_t f2tf32(float v) {
    uint32_t r; asm("cvt.rna.tf32.f32 %0, %1;" : "=r"(r) : "f"(v)); return r;
}

__device__ __forceinline__ void mma_tf32(float* c, const uint32_t* a, const uint32_t* b) {
    asm volatile("mma.sync.aligned.m16n8k8.row.col.f32.tf32.tf32.f32 "
                 "{%0,%1,%2,%3}, {%4,%5,%6,%7}, {%8,%9}, {%0,%1,%2,%3};"
                 : "+f"(c[0]), "+f"(c[1]), "+f"(c[2]), "+f"(c[3])
                 : "r"(a[0]), "r"(a[1]), "r"(a[2]), "r"(a[3]), "r"(b[0]), "r"(b[1]));
}

// ----------------------------------------------------------------------------
// Embedding
// ----------------------------------------------------------------------------
__global__ void embed_k(const float* __restrict__ tok, const float* __restrict__ pos,
                        const int* __restrict__ src) {
    int idx = blockIdx.x * blockDim.x + threadIdx.x;
    int row = idx / C_;
    int c   = idx - row * C_;
    int t   = row % T_;
    g_x[idx] = tok[(size_t)src[row] * C_ + c] + pos[t * C_ + c];
}

// ----------------------------------------------------------------------------
// LayerNorm: one block per row
// ----------------------------------------------------------------------------
__global__ void ln_k(const float* __restrict__ in, float* __restrict__ out,
                     const float* __restrict__ g, const float* __restrict__ b) {
    __shared__ float red[256];
    int row = blockIdx.x;
    int tid = threadIdx.x;
    const float* x = in + (size_t)row * C_;

    float s = 0.f, s2 = 0.f;
    for (int c = tid; c < C_; c += 256) { float v = x[c]; s += v; s2 += v * v; }

    red[tid] = s; __syncthreads();
    for (int st = 128; st > 0; st >>= 1) { if (tid < st) red[tid] += red[tid + st]; __syncthreads(); }
    float mean = red[0] * (1.f / C_);
    __syncthreads();
    red[tid] = s2; __syncthreads();
    for (int st = 128; st > 0; st >>= 1) { if (tid < st) red[tid] += red[tid + st]; __syncthreads(); }
    float var = red[0] * (1.f / C_) - mean * mean;
    float inv = rsqrtf(var + EPS_);

    for (int c = tid; c < C_; c += 256)
        out[(size_t)row * C_ + c] = (x[c] - mean) * inv * g[c] + b[c];
}

// ----------------------------------------------------------------------------
// Pack wq/wk/wv into [C, 3C]
// ----------------------------------------------------------------------------
__global__ void pack_qkv_k(const float* __restrict__ wq, const float* __restrict__ wk,
                           const float* __restrict__ wv) {
    int idx = blockIdx.x * blockDim.x + threadIdx.x;
    if (idx >= C_ * 3 * C_) return;
    int c   = idx / (3 * C_);
    int col = idx - c * (3 * C_);
    const float* w = (col < C_) ? wq : (col < 2 * C_ ? wk : wv);
    int j = col % C_;
    int h = j / HS_, d = j % HS_;
    g_wqkv[idx] = w[((size_t)h * C_ + c) * HS_ + d];
}

// ----------------------------------------------------------------------------
// TF32 tensor-core GEMM: C[M,N] (+)= A[M,K] @ B[K,N] + bias, optional ReLU.
// 128x128x32 CTA tile, 8 warps of 64x32, mma.m16n8k8, cp.async double buffer.
// Requires M%128==0, N%128==0, K%32==0 (true for all shapes here).
// ----------------------------------------------------------------------------
__device__ __forceinline__ void cp_tile(uint32_t as_base, uint32_t bs_base,
                                        const float* Ag, const float* Bg,
                                        int K, int N, int tid) {
#pragma unroll
    for (int i = 0; i < 4; i++) {
        int idx = tid + i * 256;
        int m = idx >> 3, kk = (idx & 7) << 2;
        uint32_t dst = as_base + (uint32_t)((m * AS_STRIDE + kk) * 4);
        CP16(dst, Ag + (size_t)m * K + kk);
    }
#pragma unroll
    for (int i = 0; i < 4; i++) {
        int idx = tid + i * 256;
        int kk = idx >> 5, n4 = (idx & 31) << 2;
        uint32_t dst = bs_base + (uint32_t)((kk * BS_STRIDE + n4) * 4);
        CP16(dst, Bg + (size_t)kk * N + n4);
    }
    CP_COMMIT();
}

template<bool ADD, bool RELU>
__global__ void __launch_bounds__(256)
gemm_tc(const float* __restrict__ A, const float* __restrict__ B,
        float* __restrict__ Cc, const float* __restrict__ bias,
        int K, int N) {
    extern __shared__ float sm[];
    float* Asm[2] = { sm, sm + AS_SZ };
    float* Bsm[2] = { sm + 2 * AS_SZ, sm + 2 * AS_SZ + BS_SZ };
    uint32_t sm_u32 = (uint32_t)__cvta_generic_to_shared(sm);
    uint32_t as_b[2] = { sm_u32, sm_u32 + AS_SZ * 4 };
    uint32_t bs_b[2] = { sm_u32 + 2 * AS_SZ * 4, sm_u32 + (2 * AS_SZ + BS_SZ) * 4 };

    int tid  = threadIdx.x;
    int brow = blockIdx.y * BM;
    int bcol = blockIdx.x * BN;
    int warp = tid >> 5, lane = tid & 31;
    int wm = (warp & 1) * 64, wn = (warp >> 1) * 32;
    int gid = lane >> 2, tg = lane & 3;

    float acc[4][4][4];
#pragma unroll
    for (int i = 0; i < 4; i++)
#pragma unroll
        for (int j = 0; j < 4; j++)
#pragma unroll
            for (int r = 0; r < 4; r++) acc[i][j][r] = 0.f;

    const float* Abase = A + (size_t)brow * K;
    const float* Bbase = B + bcol;

    int nk = K / BK;
    cp_tile(as_b[0], bs_b[0], Abase, Bbase, K, N, tid);

    for (int kt = 0; kt < nk; kt++) {
        int s = kt & 1;
        if (kt + 1 < nk) {
            cp_tile(as_b[s ^ 1], bs_b[s ^ 1], Abase + (kt + 1) * BK,
                    Bbase + (size_t)(kt + 1) * BK * N, K, N, tid);
            asm volatile("cp.async.wait_group 1;\n" ::: "memory");
        } else {
            asm volatile("cp.async.wait_group 0;\n" ::: "memory");
        }
        __syncthreads();

        const float* as = Asm[s];
        const float* bs = Bsm[s];
#pragma unroll
        for (int ks = 0; ks < 4; ks++) {
            int k8 = ks * 8;
            uint32_t af[4][4], bf[4][2];
#pragma unroll
            for (int mt = 0; mt < 4; mt++) {
                const float* ap = as + (wm + mt * 16 + gid) * AS_STRIDE + k8 + tg;
                af[mt][0] = f2tf32(ap[0]);
                af[mt][2] = f2tf32(ap[4]);
                af[mt][1] = f2tf32(ap[8 * AS_STRIDE]);
                af[mt][3] = f2tf32(ap[8 * AS_STRIDE + 4]);
            }
#pragma unroll
            for (int nt = 0; nt < 4; nt++) {
                const float* bp = bs + (k8 + tg) * BS_STRIDE + wn + nt * 8 + gid;
                bf[nt][0] = f2tf32(bp[0]);
                bf[nt][1] = f2tf32(bp[4 * BS_STRIDE]);
            }
#pragma unroll
            for (int mt = 0; mt < 4; mt++)
#pragma unroll
                for (int nt = 0; nt < 4; nt++)
                    mma_tf32(acc[mt][nt], af[mt], bf[nt]);
        }
        __syncthreads();
    }

    // epilogue
#pragma unroll
    for (int mt = 0; mt < 4; mt++) {
        int r0 = brow + wm + mt * 16 + gid;
#pragma unroll
        for (int nt = 0; nt < 4; nt++) {
            int c0 = bcol + wn + nt * 8 + tg * 2;
            float b0v = bias ? bias[c0] : 0.f;
            float b1v = bias ? bias[c0 + 1] : 0.f;
            float* p0 = Cc + (size_t)r0 * N + c0;
            float* p1 = Cc + (size_t)(r0 + 8) * N + c0;
            float v;
            v = acc[mt][nt][0] + b0v; if (ADD) v += p0[0]; if (RELU) v = fmaxf(v, 0.f); p0[0] = v;
            v = acc[mt][nt][1] + b1v; if (ADD) v += p0[1]; if (RELU) v = fmaxf(v, 0.f); p0[1] = v;
            v = acc[mt][nt][2] + b0v; if (ADD) v += p1[0]; if (RELU) v = fmaxf(v, 0.f); p1[0] = v;
            v = acc[mt][nt][3] + b1v; if (ADD) v += p1[1]; if (RELU) v = fmaxf(v, 0.f); p1[1] = v;
        }
    }
}

// ----------------------------------------------------------------------------
// Attention: one block (128 threads) per (t, h, b). Causal.
// ----------------------------------------------------------------------------
__global__ void attn_k() {
    __shared__ float sc[T_];
    __shared__ float qs[HS_];
    __shared__ float red[128];
    __shared__ float obuf[2][HS_];

    int t = blockIdx.x, h = blockIdx.y, b = blockIdx.z;
    int tid = threadIdx.x;
    int lane = tid & 31, w = tid >> 5;
    size_t rowbase = (size_t)(b * T_) * (3 * C_);
    int hoff = h * HS_;

    if (tid < HS_) qs[tid] = g_qkv[rowbase + (size_t)t * 3 * C_ + hoff + tid];
    __syncthreads();

    for (int j = w; j <= t; j += 4) {
        const float* kp = &g_qkv[rowbase + (size_t)j * 3 * C_ + C_ + hoff];
        float p = qs[lane] * kp[lane] + qs[lane + 32] * kp[lane + 32];
#pragma unroll
        for (int o = 16; o > 0; o >>= 1) p += __shfl_down_sync(0xffffffffu, p, o);
        if (lane == 0) sc[j] = p * SCALE_;
    }
    __syncthreads();

    float mx = -3.4e38f;
    for (int j = tid; j <= t; j += 128) mx = fmaxf(mx, sc[j]);
    red[tid] = mx; __syncthreads();
    for (int st = 64; st > 0; st >>= 1) { if (tid < st) red[tid] = fmaxf(red[tid], red[tid + st]); __syncthreads(); }
    mx = red[0]; __syncthreads();

    float s = 0.f;
    for (int j = tid; j <= t; j += 128) { float e = __expf(sc[j] - mx); sc[j] = e; s += e; }
    red[tid] = s; __syncthreads();
    for (int st = 64; st > 0; st >>= 1) { if (tid < st) red[tid] += red[tid + st]; __syncthreads(); }
    float inv = 1.f / red[0];
    __syncthreads();

    int g = tid >> 6, d = tid & 63;
    float acc = 0.f;
    for (int j = g; j <= t; j += 2)
        acc += sc[j] * g_qkv[rowbase + (size_t)j * 3 * C_ + 2 * C_ + hoff + d];
    obuf[g][d] = acc;
    __syncthreads();
    if (tid < HS_)
        g_o[(size_t)(b * T_ + t) * C_ + hoff + tid] = (obuf[0][tid] + obuf[1][tid]) * inv;
}

// ----------------------------------------------------------------------------
// Loss
// ----------------------------------------------------------------------------
__global__ void rowloss_k(const float* __restrict__ logits, const int* __restrict__ tgt) {
    __shared__ float red[256];
    int row = blockIdx.x;
    int tid = threadIdx.x;
    const float* L = logits + (size_t)row * V_;

    float mx = -3.4e38f;
    for (int j = tid; j < V_; j += 256) mx = fmaxf(mx, L[j]);
    red[tid] = mx; __syncthreads();
    for (int st = 128; st > 0; st >>= 1) { if (tid < st) red[tid] = fmaxf(red[tid], red[tid + st]); __syncthreads(); }
    mx = red[0]; __syncthreads();

    float s = 0.f;
    for (int j = tid; j < V_; j += 256) s += __expf(L[j] - mx);
    red[tid] = s; __syncthreads();
    for (int st = 128; st > 0; st >>= 1) { if (tid < st) red[tid] += red[tid + st]; __syncthreads(); }
    if (tid == 0)
        g_rowloss[row] = -(L[tgt[row]] - mx - logf(red[0]));
}

__global__ void finloss_k(float* __restrict__ out) {
    __shared__ float red[256];
    int tid = threadIdx.x;
    float s = 0.f;
    for (int j = tid; j < M_; j += 256) s += g_rowloss[j];
    red[tid] = s; __syncthreads();
    for (int st = 128; st > 0; st >>= 1) { if (tid < st) red[tid] += red[tid + st]; __syncthreads(); }
    if (tid == 0) out[0] = red[0] * (1.f / M_);
}

// ----------------------------------------------------------------------------
// Host driver
// ----------------------------------------------------------------------------
extern "C" void kernel_launch(void* const* d_in, const int* in_sizes, int n_in,
                              void* d_out, int out_size) {
    const float* tok_emb = (const float*)d_in[0];
    const float* pos_emb = (const float*)d_in[1];
    const float* wq      = (const float*)d_in[2];
    const float* wk      = (const float*)d_in[3];
    const float* wv      = (const float*)d_in[4];
    const float* wproj   = (const float*)d_in[5];
    const float* bproj   = (const float*)d_in[6];
    const float* g1      = (const float*)d_in[7];
    const float* b1      = (const float*)d_in[8];
    const float* g2      = (const float*)d_in[9];
    const float* b2      = (const float*)d_in[10];
    const float* wf1     = (const float*)d_in[11];
    const float* bf1     = (const float*)d_in[12];
    const float* wf2     = (const float*)d_in[13];
    const float* bf2     = (const float*)d_in[14];
    const float* gf      = (const float*)d_in[15];
    const float* bf      = (const float*)d_in[16];
    const float* wlm     = (const float*)d_in[17];
    const float* blm     = (const float*)d_in[18];
    const int*   sources = (const int*)d_in[19];
    const int*   targets = (const int*)d_in[20];

    float* out = (float*)d_out;
    const size_t n_logits = (size_t)M_ * V_;

    float *px, *ph, *pqkv, *po, *pwqkv, *pff;
    cudaGetSymbolAddress((void**)&px,    g_x);
    cudaGetSymbolAddress((void**)&ph,    g_h);
    cudaGetSymbolAddress((void**)&pqkv,  g_qkv);
    cudaGetSymbolAddress((void**)&po,    g_o);
    cudaGetSymbolAddress((void**)&pwqkv, g_wqkv);
    cudaGetSymbolAddress((void**)&pff,   g_ff);

    cudaFuncSetAttribute(gemm_tc<false, false>, cudaFuncAttributeMaxDynamicSharedMemorySize, SMEM_BYTES);
    cudaFuncSetAttribute(gemm_tc<true,  false>, cudaFuncAttributeMaxDynamicSharedMemorySize, SMEM_BYTES);
    cudaFuncSetAttribute(gemm_tc<false, true >, cudaFuncAttributeMaxDynamicSharedMemorySize, SMEM_BYTES);

    // 1. embedding
    embed_k<<<(M_ * C_) / 256, 256>>>(tok_emb, pos_emb, sources);

    // 2. transformer blocks
    for (int i = 0; i < NB_; i++) {
        const float* wq_i = wq + (size_t)i * H_ * C_ * HS_;
        const float* wk_i = wk + (size_t)i * H_ * C_ * HS_;
        const float* wv_i = wv + (size_t)i * H_ * C_ * HS_;

        ln_k<<<M_, 256>>>(px, ph, g1 + i * C_, b1 + i * C_);
        pack_qkv_k<<<(C_ * 3 * C_ + 255) / 256, 256>>>(wq_i, wk_i, wv_i);

        // qkv = h @ Wqkv : [4096, 2304]
        gemm_tc<false, false><<<dim3((3 * C_) / BN, M_ / BM), 256, SMEM_BYTES>>>(
            ph, pwqkv, pqkv, nullptr, C_, 3 * C_);

        attn_k<<<dim3(T_, H_, B_), 128>>>();

        // x += o @ wproj + bproj
        gemm_tc<true, false><<<dim3(C_ / BN, M_ / BM), 256, SMEM_BYTES>>>(
            po, wproj + (size_t)i * C_ * C_, px, bproj + i * C_, C_, C_);

        ln_k<<<M_, 256>>>(px, ph, g2 + i * C_, b2 + i * C_);

        // ff = relu(h @ wf1 + bf1)
        gemm_tc<false, true><<<dim3(FF_ / BN, M_ / BM), 256, SMEM_BYTES>>>(
            ph, wf1 + (size_t)i * C_ * FF_, pff, bf1 + i * FF_, C_, FF_);

        // x += ff @ wf2 + bf2
        gemm_tc<true, false><<<dim3(C_ / BN, M_ / BM), 256, SMEM_BYTES>>>(
            pff, wf2 + (size_t)i * FF_ * C_, px, bf2 + i * C_, FF_, C_);
    }

    // 3. final LN + LM head -> d_out
    ln_k<<<M_, 256>>>(px, ph, gf, bf);
    gemm_tc<false, false><<<dim3(V_ / BN, M_ / BM), 256, SMEM_BYTES>>>(
        ph, wlm, out, blm, C_, V_);

    // 4. loss
    rowloss_k<<<M_, 256>>>(out, targets);
    if ((size_t)out_size > n_logits)
        finloss_k<<<1, 256>>>(out + n_logits);
}

// round 3
// speedup vs baseline: 3.6504x; 1.6503x over previous
#include <cuda_runtime.h>
#include <cstdint>
#include <math.h>

// Problem constants
#define V_   32000
#define C_   768
#define T_   1024
#define H_   12
#define HS_  64
#define FF_  9216
#define NB_  3
#define B_   4
#define M_   (B_ * T_)
#define EPS_ 1e-5f
#define SCALE_ 0.03608439182435161f   // 768^-0.5

// GEMM tiling
#define BM 128
#define BN 128
#define BK 32
#define AS_STRIDE 36
#define BS_STRIDE 136
#define AS_SZ (BM * AS_STRIDE)
#define BS_SZ (BK * BS_STRIDE)
#define SMEM_BYTES (2 * (AS_SZ + BS_SZ) * 4)

// Attention tiling
#define ALD 68
#define ATT_SMEM (3 * 64 * ALD * 4)   // Qs/Ps + Ks + Vs = 52224 B

// Epilogue modes
#define MODE_PLAIN 0
#define MODE_ROUND 1
#define MODE_ADD 2
#define MODE_RELU_ROUND 3

// ----------------------------------------------------------------------------
// Scratch (static device globals)
// ----------------------------------------------------------------------------
__device__ float g_x[M_ * C_];
__device__ float g_h[M_ * C_];
__device__ float g_qkv[M_ * 3 * C_];
__device__ float g_o[M_ * C_];
__device__ float g_wqkv[C_ * 3 * C_];
__device__ float g_wproj[NB_ * C_ * C_];
__device__ float g_wf1[(size_t)NB_ * C_ * FF_];
__device__ float g_wf2[(size_t)NB_ * FF_ * C_];
__device__ float g_wlm[(size_t)C_ * V_];
__device__ float g_ff[(size_t)M_ * FF_];
__device__ float g_rowloss[M_];

// ----------------------------------------------------------------------------
// PTX helpers
// ----------------------------------------------------------------------------
#define CP16(dst, src) asm volatile("cp.async.cg.shared.global [%0], [%1], 16;\n" :: "r"(dst), "l"(src) : "memory")
#define CP_COMMIT() asm volatile("cp.async.commit_group;\n" ::: "memory")

__device__ __forceinline__ uint32_t f2tf32(float v) {
    uint32_t r; asm("cvt.rna.tf32.f32 %0, %1;" : "=r"(r) : "f"(v)); return r;
}
__device__ __forceinline__ float roundtf(float v) {
    return __uint_as_float(f2tf32(v));
}

__device__ __forceinline__ void mma_tf32(float* c, const uint32_t* a, const uint32_t* b) {
    asm volatile("mma.sync.aligned.m16n8k8.row.col.f32.tf32.tf32.f32 "
                 "{%0,%1,%2,%3}, {%4,%5,%6,%7}, {%8,%9}, {%0,%1,%2,%3};"
                 : "+f"(c[0]), "+f"(c[1]), "+f"(c[2]), "+f"(c[3])
                 : "r"(a[0]), "r"(a[1]), "r"(a[2]), "r"(a[3]), "r"(b[0]), "r"(b[1]));
}

// ----------------------------------------------------------------------------
// Weight pre-round: out[i] = tf32_rna(in[i])
// ----------------------------------------------------------------------------
__global__ void round_w_k(const float* __restrict__ in, float* __restrict__ out, size_t n) {
    size_t i = (size_t)blockIdx.x * blockDim.x + threadIdx.x;
    if (i < n) out[i] = roundtf(in[i]);
}

// ----------------------------------------------------------------------------
// Embedding
// ----------------------------------------------------------------------------
__global__ void embed_k(const float* __restrict__ tok, const float* __restrict__ pos,
                        const int* __restrict__ src) {
    int idx = blockIdx.x * blockDim.x + threadIdx.x;
    int row = idx / C_;
    int c   = idx - row * C_;
    int t   = row % T_;
    g_x[idx] = tok[(size_t)src[row] * C_ + c] + pos[t * C_ + c];
}

// ----------------------------------------------------------------------------
// LayerNorm (output tf32-rounded; feeds GEMM A-side)
// ----------------------------------------------------------------------------
__global__ void ln_k(const float* __restrict__ in, float* __restrict__ out,
                     const float* __restrict__ g, const float* __restrict__ b) {
    __shared__ float red[256];
    int row = blockIdx.x;
    int tid = threadIdx.x;
    const float* x = in + (size_t)row * C_;

    float s = 0.f, s2 = 0.f;
    for (int c = tid; c < C_; c += 256) { float v = x[c]; s += v; s2 += v * v; }

    red[tid] = s; __syncthreads();
    for (int st = 128; st > 0; st >>= 1) { if (tid < st) red[tid] += red[tid + st]; __syncthreads(); }
    float mean = red[0] * (1.f / C_);
    __syncthreads();
    red[tid] = s2; __syncthreads();
    for (int st = 128; st > 0; st >>= 1) { if (tid < st) red[tid] += red[tid + st]; __syncthreads(); }
    float var = red[0] * (1.f / C_) - mean * mean;
    float inv = rsqrtf(var + EPS_);

    for (int c = tid; c < C_; c += 256)
        out[(size_t)row * C_ + c] = roundtf((x[c] - mean) * inv * g[c] + b[c]);
}

// ----------------------------------------------------------------------------
// Pack + round wq/wk/wv into [C, 3C]
// ----------------------------------------------------------------------------
__global__ void pack_qkv_k(const float* __restrict__ wq, const float* __restrict__ wk,
                           const float* __restrict__ wv) {
    int idx = blockIdx.x * blockDim.x + threadIdx.x;
    if (idx >= C_ * 3 * C_) return;
    int c   = idx / (3 * C_);
    int col = idx - c * (3 * C_);
    const float* w = (col < C_) ? wq : (col < 2 * C_ ? wk : wv);
    int j = col % C_;
    int h = j / HS_, d = j % HS_;
    g_wqkv[idx] = roundtf(w[((size_t)h * C_ + c) * HS_ + d]);
}

// ----------------------------------------------------------------------------
// TF32 tensor-core GEMM (operands pre-rounded; no in-loop cvt)
// ----------------------------------------------------------------------------
__device__ __forceinline__ void cp_tile(uint32_t as_base, uint32_t bs_base,
                                        const float* Ag, const float* Bg,
                                        int K, int N, int tid) {
#pragma unroll
    for (int i = 0; i < 4; i++) {
        int idx = tid + i * 256;
        int m = idx >> 3, kk = (idx & 7) << 2;
        uint32_t dst = as_base + (uint32_t)((m * AS_STRIDE + kk) * 4);
        CP16(dst, Ag + (size_t)m * K + kk);
    }
#pragma unroll
    for (int i = 0; i < 4; i++) {
        int idx = tid + i * 256;
        int kk = idx >> 5, n4 = (idx & 31) << 2;
        uint32_t dst = bs_base + (uint32_t)((kk * BS_STRIDE + n4) * 4);
        CP16(dst, Bg + (size_t)kk * N + n4);
    }
    CP_COMMIT();
}

template<int MODE>
__global__ void __launch_bounds__(256)
gemm_tc(const float* __restrict__ A, const float* __restrict__ B,
        float* __restrict__ Cc, const float* __restrict__ bias,
        int K, int N) {
    extern __shared__ float sm[];
    uint32_t sm_u32 = (uint32_t)__cvta_generic_to_shared(sm);
    uint32_t as_b[2] = { sm_u32, sm_u32 + AS_SZ * 4 };
    uint32_t bs_b[2] = { sm_u32 + 2 * AS_SZ * 4, sm_u32 + (2 * AS_SZ + BS_SZ) * 4 };
    const uint32_t* Asm[2] = { (const uint32_t*)sm, (const uint32_t*)(sm + AS_SZ) };
    const uint32_t* Bsm[2] = { (const uint32_t*)(sm + 2 * AS_SZ), (const uint32_t*)(sm + 2 * AS_SZ + BS_SZ) };

    int tid  = threadIdx.x;
    int brow = blockIdx.y * BM;
    int bcol = blockIdx.x * BN;
    int warp = tid >> 5, lane = tid & 31;
    int wm = (warp & 1) * 64, wn = (warp >> 1) * 32;
    int gid = lane >> 2, tg = lane & 3;

    float acc[4][4][4];
#pragma unroll
    for (int i = 0; i < 4; i++)
#pragma unroll
        for (int j = 0; j < 4; j++)
#pragma unroll
            for (int r = 0; r < 4; r++) acc[i][j][r] = 0.f;

    const float* Abase = A + (size_t)brow * K;
    const float* Bbase = B + bcol;

    int nk = K / BK;
    cp_tile(as_b[0], bs_b[0], Abase, Bbase, K, N, tid);

    for (int kt = 0; kt < nk; kt++) {
        int s = kt & 1;
        if (kt + 1 < nk) {
            cp_tile(as_b[s ^ 1], bs_b[s ^ 1], Abase + (kt + 1) * BK,
                    Bbase + (size_t)(kt + 1) * BK * N, K, N, tid);
            asm volatile("cp.async.wait_group 1;\n" ::: "memory");
        } else {
            asm volatile("cp.async.wait_group 0;\n" ::: "memory");
        }
        __syncthreads();

        const uint32_t* as = Asm[s];
        const uint32_t* bs = Bsm[s];
#pragma unroll
        for (int ks = 0; ks < 4; ks++) {
            int k8 = ks * 8;
            uint32_t af[4][4], bf[4][2];
#pragma unroll
            for (int mt = 0; mt < 4; mt++) {
                const uint32_t* ap = as + (wm + mt * 16 + gid) * AS_STRIDE + k8 + tg;
                af[mt][0] = ap[0];
                af[mt][2] = ap[4];
                af[mt][1] = ap[8 * AS_STRIDE];
                af[mt][3] = ap[8 * AS_STRIDE + 4];
            }
#pragma unroll
            for (int nt = 0; nt < 4; nt++) {
                const uint32_t* bp = bs + (k8 + tg) * BS_STRIDE + wn + nt * 8 + gid;
                bf[nt][0] = bp[0];
                bf[nt][1] = bp[4 * BS_STRIDE];
            }
#pragma unroll
            for (int mt = 0; mt < 4; mt++)
#pragma unroll
                for (int nt = 0; nt < 4; nt++)
                    mma_tf32(acc[mt][nt], af[mt], bf[nt]);
        }
        __syncthreads();
    }

    // epilogue
#pragma unroll
    for (int mt = 0; mt < 4; mt++) {
        int r0 = brow + wm + mt * 16 + gid;
#pragma unroll
        for (int nt = 0; nt < 4; nt++) {
            int c0 = bcol + wn + nt * 8 + tg * 2;
            float b0v = bias ? bias[c0] : 0.f;
            float b1v = bias ? bias[c0 + 1] : 0.f;
            float* p0 = Cc + (size_t)r0 * N + c0;
            float* p1 = Cc + (size_t)(r0 + 8) * N + c0;
            float v0 = acc[mt][nt][0] + b0v, v1 = acc[mt][nt][1] + b1v;
            float v2 = acc[mt][nt][2] + b0v, v3 = acc[mt][nt][3] + b1v;
            if (MODE == MODE_ADD) { v0 += p0[0]; v1 += p0[1]; v2 += p1[0]; v3 += p1[1]; }
            if (MODE == MODE_RELU_ROUND) {
                v0 = fmaxf(v0, 0.f); v1 = fmaxf(v1, 0.f); v2 = fmaxf(v2, 0.f); v3 = fmaxf(v3, 0.f);
            }
            if (MODE == MODE_ROUND || MODE == MODE_RELU_ROUND) {
                v0 = roundtf(v0); v1 = roundtf(v1); v2 = roundtf(v2); v3 = roundtf(v3);
            }
            p0[0] = v0; p0[1] = v1; p1[0] = v2; p1[1] = v3;
        }
    }
}

// ----------------------------------------------------------------------------
// Flash attention: block = (qtile 64, h, b), 4 warps, TF32 mma, online softmax
// ----------------------------------------------------------------------------
__global__ void __launch_bounds__(128) attn_flash() {
    extern __shared__ float asm_[];
    float (*Qs)[ALD] = (float(*)[ALD])asm_;                       // reused as Ps
    float (*Ks)[ALD] = (float(*)[ALD])(asm_ + 64 * ALD);
    float (*Vs)[ALD] = (float(*)[ALD])(asm_ + 2 * 64 * ALD);

    int qi = blockIdx.x, h = blockIdx.y, b = blockIdx.z;
    int q0 = qi * 64;
    int tid = threadIdx.x, lane = tid & 31, w = tid >> 5;
    int gid = lane >> 2, tg = lane & 3;
    size_t base = (size_t)(b * T_) * (3 * C_);
    int hoff = h * HS_;

    // load Q tile -> smem
    for (int i = tid; i < 64 * 16; i += 128) {
        int r = i >> 4, c4 = (i & 15) << 2;
        *(float4*)&Qs[r][c4] = *(const float4*)&g_qkv[base + (size_t)(q0 + r) * 3 * C_ + hoff + c4];
    }
    __syncthreads();

    // Q fragments (values already tf32-rounded by QKV epilogue)
    uint32_t qf[8][4];
#pragma unroll
    for (int ks = 0; ks < 8; ks++) {
        const float* ap = &Qs[w * 16 + gid][ks * 8 + tg];
        qf[ks][0] = __float_as_uint(ap[0]);
        qf[ks][1] = __float_as_uint(ap[8 * ALD]);
        qf[ks][2] = __float_as_uint(ap[4]);
        qf[ks][3] = __float_as_uint(ap[8 * ALD + 4]);
    }

    float m0 = -1e30f, m1 = -1e30f, l0 = 0.f, l1 = 0.f;
    float acc_o[8][4];
#pragma unroll
    for (int nt = 0; nt < 8; nt++)
#pragma unroll
        for (int r = 0; r < 4; r++) acc_o[nt][r] = 0.f;

    int row0 = q0 + w * 16 + gid;
    int row1 = row0 + 8;
    float (*Pw)[ALD] = (float(*)[ALD])(asm_ + (size_t)w * 16 * ALD);

    for (int j0 = 0; j0 <= q0; j0 += 64) {
        __syncthreads();
        for (int i = tid; i < 64 * 16; i += 128) {
            int r = i >> 4, c4 = (i & 15) << 2;
            size_t rb = base + (size_t)(j0 + r) * 3 * C_ + hoff + c4;
            *(float4*)&Ks[r][c4] = *(const float4*)&g_qkv[rb + C_];
            *(float4*)&Vs[r][c4] = *(const float4*)&g_qkv[rb + 2 * C_];
        }
        __syncthreads();

        // S = Q @ K^T
        float sc[8][4];
#pragma unroll
        for (int nt = 0; nt < 8; nt++)
#pragma unroll
            for (int r = 0; r < 4; r++) sc[nt][r] = 0.f;
#pragma unroll
        for (int ks = 0; ks < 8; ks++) {
#pragma unroll
            for (int nt = 0; nt < 8; nt++) {
                uint32_t bf[2];
                bf[0] = __float_as_uint(Ks[nt * 8 + gid][ks * 8 + tg]);
                bf[1] = __float_as_uint(Ks[nt * 8 + gid][ks * 8 + tg + 4]);
                mma_tf32(sc[nt], qf[ks], bf);
            }
        }

        bool diag = (j0 == q0);
#pragma unroll
        for (int nt = 0; nt < 8; nt++) {
            sc[nt][0] *= SCALE_; sc[nt][1] *= SCALE_;
            sc[nt][2] *= SCALE_; sc[nt][3] *= SCALE_;
            if (diag) {
                int jg = j0 + nt * 8 + tg * 2;
                if (jg > row0)     sc[nt][0] = -1e30f;
                if (jg + 1 > row0) sc[nt][1] = -1e30f;
                if (jg > row1)     sc[nt][2] = -1e30f;
                if (jg + 1 > row1) sc[nt][3] = -1e30f;
            }
        }

        // row max
        float mx0 = -1e30f, mx1 = -1e30f;
#pragma unroll
        for (int nt = 0; nt < 8; nt++) {
            mx0 = fmaxf(mx0, fmaxf(sc[nt][0], sc[nt][1]));
            mx1 = fmaxf(mx1, fmaxf(sc[nt][2], sc[nt][3]));
        }
        mx0 = fmaxf(mx0, __shfl_xor_sync(0xffffffffu, mx0, 1));
        mx0 = fmaxf(mx0, __shfl_xor_sync(0xffffffffu, mx0, 2));
        mx1 = fmaxf(mx1, __shfl_xor_sync(0xffffffffu, mx1, 1));
        mx1 = fmaxf(mx1, __shfl_xor_sync(0xffffffffu, mx1, 2));

        float mn0 = fmaxf(m0, mx0), mn1 = fmaxf(m1, mx1);
        float a0 = __expf(m0 - mn0), a1 = __expf(m1 - mn1);
        m0 = mn0; m1 = mn1;

        float s0 = 0.f, s1 = 0.f;
#pragma unroll
        for (int nt = 0; nt < 8; nt++) {
            float p0 = __expf(sc[nt][0] - mn0), p1 = __expf(sc[nt][1] - mn0);
            float p2 = __expf(sc[nt][2] - mn1), p3 = __expf(sc[nt][3] - mn1);
            s0 += p0 + p1; s1 += p2 + p3;
            // store P tf32-rounded to per-warp smem region
            Pw[gid][nt * 8 + 2 * tg]     = roundtf(p0);
            Pw[gid][nt * 8 + 2 * tg + 1] = roundtf(p1);
            Pw[gid + 8][nt * 8 + 2 * tg]     = roundtf(p2);
            Pw[gid + 8][nt * 8 + 2 * tg + 1] = roundtf(p3);
        }
        s0 += __shfl_xor_sync(0xffffffffu, s0, 1);
        s0 += __shfl_xor_sync(0xffffffffu, s0, 2);
        s1 += __shfl_xor_sync(0xffffffffu, s1, 1);
        s1 += __shfl_xor_sync(0xffffffffu, s1, 2);
        l0 = l0 * a0 + s0;
        l1 = l1 * a1 + s1;

#pragma unroll
        for (int nt = 0; nt < 8; nt++) {
            acc_o[nt][0] *= a0; acc_o[nt][1] *= a0;
            acc_o[nt][2] *= a1; acc_o[nt][3] *= a1;
        }
        __syncwarp();

        // O += P @ V
#pragma unroll
        for (int ks = 0; ks < 8; ks++) {
            uint32_t af[4];
            const float* pp = &Pw[gid][ks * 8 + tg];
            af[0] = __float_as_uint(pp[0]);
            af[1] = __float_as_uint(pp[8 * ALD]);
            af[2] = __float_as_uint(pp[4]);
            af[3] = __float_as_uint(pp[8 * ALD + 4]);
#pragma unroll
            for (int nt = 0; nt < 8; nt++) {
                uint32_t bf[2];
                bf[0] = __float_as_uint(Vs[ks * 8 + tg][nt * 8 + gid]);
                bf[1] = __float_as_uint(Vs[ks * 8 + tg + 4][nt * 8 + gid]);
                mma_tf32(acc_o[nt], af, bf);
            }
        }
        __syncwarp();
    }

    // epilogue: normalize, round, store
    float i0 = 1.f / l0, i1 = 1.f / l1;
#pragma unroll
    for (int nt = 0; nt < 8; nt++) {
        float2 v0 = make_float2(roundtf(acc_o[nt][0] * i0), roundtf(acc_o[nt][1] * i0));
        float2 v1 = make_float2(roundtf(acc_o[nt][2] * i1), roundtf(acc_o[nt][3] * i1));
        *(float2*)&g_o[(size_t)(b * T_ + row0) * C_ + hoff + nt * 8 + 2 * tg] = v0;
        *(float2*)&g_o[(size_t)(b * T_ + row1) * C_ + hoff + nt * 8 + 2 * tg] = v1;
    }
}

// ----------------------------------------------------------------------------
// Loss
// ----------------------------------------------------------------------------
__global__ void rowloss_k(const float* __restrict__ logits, const int* __restrict__ tgt) {
    __shared__ float red[256];
    int row = blockIdx.x;
    int tid = threadIdx.x;
    const float* L = logits + (size_t)row * V_;

    float mx = -3.4e38f;
    for (int j = tid; j < V_; j += 256) mx = fmaxf(mx, L[j]);
    red[tid] = mx; __syncthreads();
    for (int st = 128; st > 0; st >>= 1) { if (tid < st) red[tid] = fmaxf(red[tid], red[tid + st]); __syncthreads(); }
    mx = red[0]; __syncthreads();

    float s = 0.f;
    for (int j = tid; j < V_; j += 256) s += __expf(L[j] - mx);
    red[tid] = s; __syncthreads();
    for (int st = 128; st > 0; st >>= 1) { if (tid < st) red[tid] += red[tid + st]; __syncthreads(); }
    if (tid == 0)
        g_rowloss[row] = -(L[tgt[row]] - mx - logf(red[0]));
}

__global__ void finloss_k(float* __restrict__ out) {
    __shared__ float red[256];
    int tid = threadIdx.x;
    float s = 0.f;
    for (int j = tid; j < M_; j += 256) s += g_rowloss[j];
    red[tid] = s; __syncthreads();
    for (int st = 128; st > 0; st >>= 1) { if (tid < st) red[tid] += red[tid + st]; __syncthreads(); }
    if (tid == 0) out[0] = red[0] * (1.f / M_);
}

// ----------------------------------------------------------------------------
// Host driver
// ----------------------------------------------------------------------------
extern "C" void kernel_launch(void* const* d_in, const int* in_sizes, int n_in,
                              void* d_out, int out_size) {
    const float* tok_emb = (const float*)d_in[0];
    const float* pos_emb = (const float*)d_in[1];
    const float* wq      = (const float*)d_in[2];
    const float* wk      = (const float*)d_in[3];
    const float* wv      = (const float*)d_in[4];
    const float* wproj   = (const float*)d_in[5];
    const float* bproj   = (const float*)d_in[6];
    const float* g1      = (const float*)d_in[7];
    const float* b1      = (const float*)d_in[8];
    const float* g2      = (const float*)d_in[9];
    const float* b2      = (const float*)d_in[10];
    const float* wf1     = (const float*)d_in[11];
    const float* bf1     = (const float*)d_in[12];
    const float* wf2     = (const float*)d_in[13];
    const float* bf2     = (const float*)d_in[14];
    const float* gf      = (const float*)d_in[15];
    const float* bf      = (const float*)d_in[16];
    const float* wlm     = (const float*)d_in[17];
    const float* blm     = (const float*)d_in[18];
    const int*   sources = (const int*)d_in[19];
    const int*   targets = (const int*)d_in[20];

    float* out = (float*)d_out;
    const size_t n_logits = (size_t)M_ * V_;

    float *px, *ph, *pqkv, *po, *pwqkv, *pff, *pwproj, *pwf1, *pwf2, *pwlm;
    cudaGetSymbolAddress((void**)&px,     g_x);
    cudaGetSymbolAddress((void**)&ph,     g_h);
    cudaGetSymbolAddress((void**)&pqkv,   g_qkv);
    cudaGetSymbolAddress((void**)&po,     g_o);
    cudaGetSymbolAddress((void**)&pwqkv,  g_wqkv);
    cudaGetSymbolAddress((void**)&pff,    g_ff);
    cudaGetSymbolAddress((void**)&pwproj, g_wproj);
    cudaGetSymbolAddress((void**)&pwf1,   g_wf1);
    cudaGetSymbolAddress((void**)&pwf2,   g_wf2);
    cudaGetSymbolAddress((void**)&pwlm,   g_wlm);

    cudaFuncSetAttribute(gemm_tc<MODE_PLAIN>,      cudaFuncAttributeMaxDynamicSharedMemorySize, SMEM_BYTES);
    cudaFuncSetAttribute(gemm_tc<MODE_ROUND>,      cudaFuncAttributeMaxDynamicSharedMemorySize, SMEM_BYTES);
    cudaFuncSetAttribute(gemm_tc<MODE_ADD>,        cudaFuncAttributeMaxDynamicSharedMemorySize, SMEM_BYTES);
    cudaFuncSetAttribute(gemm_tc<MODE_RELU_ROUND>, cudaFuncAttributeMaxDynamicSharedMemorySize, SMEM_BYTES);
    cudaFuncSetAttribute(attn_flash, cudaFuncAttributeMaxDynamicSharedMemorySize, ATT_SMEM);

    // 0. pre-round weights to tf32
    {
        size_t n;
        n = (size_t)NB_ * C_ * C_;
        round_w_k<<<(unsigned)((n + 255) / 256), 256>>>(wproj, pwproj, n);
        n = (size_t)NB_ * C_ * FF_;
        round_w_k<<<(unsigned)((n + 255) / 256), 256>>>(wf1, pwf1, n);
        round_w_k<<<(unsigned)((n + 255) / 256), 256>>>(wf2, pwf2, n);
        n = (size_t)C_ * V_;
        round_w_k<<<(unsigned)((n + 255) / 256), 256>>>(wlm, pwlm, n);
    }

    // 1. embedding
    embed_k<<<(M_ * C_) / 256, 256>>>(tok_emb, pos_emb, sources);

    // 2. transformer blocks
    for (int i = 0; i < NB_; i++) {
        const float* wq_i = wq + (size_t)i * H_ * C_ * HS_;
        const float* wk_i = wk + (size_t)i * H_ * C_ * HS_;
        const float* wv_i = wv + (size_t)i * H_ * C_ * HS_;

        ln_k<<<M_, 256>>>(px, ph, g1 + i * C_, b1 + i * C_);
        pack_qkv_k<<<(C_ * 3 * C_ + 255) / 256, 256>>>(wq_i, wk_i, wv_i);

        gemm_tc<MODE_ROUND><<<dim3((3 * C_) / BN, M_ / BM), 256, SMEM_BYTES>>>(
            ph, pwqkv, pqkv, nullptr, C_, 3 * C_);

        attn_flash<<<dim3(T_ / 64, H_, B_), 128, ATT_SMEM>>>();

        gemm_tc<MODE_ADD><<<dim3(C_ / BN, M_ / BM), 256, SMEM_BYTES>>>(
            po, pwproj + (size_t)i * C_ * C_, px, bproj + i * C_, C_, C_);

        ln_k<<<M_, 256>>>(px, ph, g2 + i * C_, b2 + i * C_);

        gemm_tc<MODE_RELU_ROUND><<<dim3(FF_ / BN, M_ / BM), 256, SMEM_BYTES>>>(
            ph, pwf1 + (size_t)i * C_ * FF_, pff, bf1 + i * FF_, C_, FF_);

        gemm_tc<MODE_ADD><<<dim3(C_ / BN, M_ / BM), 256, SMEM_BYTES>>>(
            pff, pwf2 + (size_t)i * FF_ * C_, px, bf2 + i * C_, FF_, C_);
    }

    // 3. final LN + LM head
    ln_k<<<M_, 256>>>(px, ph, gf, bf);
    gemm_tc<MODE_PLAIN><<<dim3(V_ / BN, M_ / BM), 256, SMEM_BYTES>>>(
        ph, pwlm, out, blm, C_, V_);

    // 4. loss
    rowloss_k<<<M_, 256>>>(out, targets);
    if ((size_t)out_size > n_logits)
        finloss_k<<<1, 256>>>(out + n_logits);
}

// round 4
// speedup vs baseline: 3.9017x; 1.0688x over previous
#include <cuda_runtime.h>
#include <cstdint>
#include <math.h>

// Problem constants
#define V_   32000
#define C_   768
#define T_   1024
#define H_   12
#define HS_  64
#define FF_  9216
#define NB_  3
#define B_   4
#define M_   (B_ * T_)
#define EPS_ 1e-5f
#define SCALE_ 0.03608439182435161f   // 768^-0.5

// GEMM tiling
#define BM 128
#define BK 32
#define AS_STRIDE 36
#define AS_SZ (BM * AS_STRIDE)

// Attention tiling
#define ALD 68
#define ATT_SMEM (3 * 64 * ALD * 4)

// Epilogue modes
#define MODE_PLAIN 0
#define MODE_ROUND 1
#define MODE_ADD 2
#define MODE_RELU_ROUND 3

// ----------------------------------------------------------------------------
// Scratch
// ----------------------------------------------------------------------------
__device__ float g_x[M_ * C_];
__device__ float g_h[M_ * C_];
__device__ float g_qkv[M_ * 3 * C_];
__device__ float g_o[M_ * C_];
__device__ float g_wqkv[C_ * 3 * C_];
__device__ float g_wproj[NB_ * C_ * C_];
__device__ float g_wf1[(size_t)NB_ * C_ * FF_];
__device__ float g_wf2[(size_t)NB_ * FF_ * C_];
__device__ float g_wlm[(size_t)C_ * V_];
__device__ float g_ff[(size_t)M_ * FF_];
__device__ float g_rowloss[M_];

// ----------------------------------------------------------------------------
// PTX helpers
// ----------------------------------------------------------------------------
#define CP16(dst, src) asm volatile("cp.async.cg.shared.global [%0], [%1], 16;\n" :: "r"(dst), "l"(src) : "memory")
#define CP_COMMIT() asm volatile("cp.async.commit_group;\n" ::: "memory")

__device__ __forceinline__ uint32_t f2tf32(float v) {
    uint32_t r; asm("cvt.rna.tf32.f32 %0, %1;" : "=r"(r) : "f"(v)); return r;
}
__device__ __forceinline__ float roundtf(float v) {
    return __uint_as_float(f2tf32(v));
}

__device__ __forceinline__ void mma_tf32(float* c, const uint32_t* a, const uint32_t* b) {
    asm volatile("mma.sync.aligned.m16n8k8.row.col.f32.tf32.tf32.f32 "
                 "{%0,%1,%2,%3}, {%4,%5,%6,%7}, {%8,%9}, {%0,%1,%2,%3};"
                 : "+f"(c[0]), "+f"(c[1]), "+f"(c[2]), "+f"(c[3])
                 : "r"(a[0]), "r"(a[1]), "r"(a[2]), "r"(a[3]), "r"(b[0]), "r"(b[1]));
}

// ----------------------------------------------------------------------------
// Weight pre-round (float4)
// ----------------------------------------------------------------------------
__global__ void round_w_k(const float4* __restrict__ in, float4* __restrict__ out, size_t n4) {
    size_t i = (size_t)blockIdx.x * blockDim.x + threadIdx.x;
    if (i < n4) {
        float4 v = in[i];
        out[i] = make_float4(roundtf(v.x), roundtf(v.y), roundtf(v.z), roundtf(v.w));
    }
}

// ----------------------------------------------------------------------------
// Embedding (float4)
// ----------------------------------------------------------------------------
__global__ void embed_k(const float4* __restrict__ tok, const float4* __restrict__ pos,
                        const int* __restrict__ src) {
    int idx = blockIdx.x * blockDim.x + threadIdx.x;   // M_*192
    int row = idx / 192;
    int c4  = idx - row * 192;
    int t   = row % T_;
    float4 a = tok[(size_t)src[row] * 192 + c4];
    float4 p = pos[t * 192 + c4];
    ((float4*)g_x)[idx] = make_float4(a.x + p.x, a.y + p.y, a.z + p.z, a.w + p.w);
}

// ----------------------------------------------------------------------------
// LayerNorm: warp per row, float4, shuffle reductions. Output tf32-rounded.
// ----------------------------------------------------------------------------
__global__ void __launch_bounds__(256) ln_k(const float* __restrict__ in, float* __restrict__ out,
                                            const float* __restrict__ g, const float* __restrict__ b) {
    int warp = threadIdx.x >> 5, lane = threadIdx.x & 31;
    int row = blockIdx.x * 8 + warp;
    const float4* x4 = (const float4*)(in + (size_t)row * C_);

    float4 v[6];
    float s = 0.f, s2 = 0.f;
#pragma unroll
    for (int i = 0; i < 6; i++) {
        v[i] = x4[lane + 32 * i];
        s  += v[i].x + v[i].y + v[i].z + v[i].w;
        s2 += v[i].x * v[i].x + v[i].y * v[i].y + v[i].z * v[i].z + v[i].w * v[i].w;
    }
#pragma unroll
    for (int o = 16; o > 0; o >>= 1) {
        s  += __shfl_xor_sync(0xffffffffu, s, o);
        s2 += __shfl_xor_sync(0xffffffffu, s2, o);
    }
    float mean = s * (1.f / C_);
    float var  = s2 * (1.f / C_) - mean * mean;
    float inv  = rsqrtf(var + EPS_);

    const float4* g4 = (const float4*)g;
    const float4* b4 = (const float4*)b;
    float4* o4 = (float4*)(out + (size_t)row * C_);
#pragma unroll
    for (int i = 0; i < 6; i++) {
        float4 gg = g4[lane + 32 * i], bb = b4[lane + 32 * i];
        float4 r;
        r.x = roundtf((v[i].x - mean) * inv * gg.x + bb.x);
        r.y = roundtf((v[i].y - mean) * inv * gg.y + bb.y);
        r.z = roundtf((v[i].z - mean) * inv * gg.z + bb.z);
        r.w = roundtf((v[i].w - mean) * inv * gg.w + bb.w);
        o4[lane + 32 * i] = r;
    }
}

// ----------------------------------------------------------------------------
// Pack + round wq/wk/wv into [C, 3C]
// ----------------------------------------------------------------------------
__global__ void pack_qkv_k(const float* __restrict__ wq, const float* __restrict__ wk,
                           const float* __restrict__ wv) {
    int idx = blockIdx.x * blockDim.x + threadIdx.x;
    if (idx >= C_ * 3 * C_) return;
    int c   = idx / (3 * C_);
    int col = idx - c * (3 * C_);
    const float* w = (col < C_) ? wq : (col < 2 * C_ ? wk : wv);
    int j = col % C_;
    int h = j / HS_, d = j % HS_;
    g_wqkv[idx] = roundtf(w[((size_t)h * C_ + c) * HS_ + d]);
}

// ----------------------------------------------------------------------------
// TF32 tensor-core GEMM, templated tile width.
// TBN=128: 8 warps of 64x32 (2 CTAs/SM). TBN=256: 8 warps of 64x64.
// ----------------------------------------------------------------------------
template<int TBN>
__device__ __forceinline__ void cp_tile(uint32_t as_base, uint32_t bs_base,
                                        const float* Ag, const float* Bg,
                                        int K, int N, int tid) {
    constexpr int BSTR = TBN + 8;
#pragma unroll
    for (int i = 0; i < 4; i++) {
        int idx = tid + i * 256;
        int m = idx >> 3, kk = (idx & 7) << 2;
        CP16(as_base + (uint32_t)((m * AS_STRIDE + kk) * 4), Ag + (size_t)m * K + kk);
    }
    constexpr int BITERS = TBN / 32;
    constexpr int NQ = TBN / 4;        // float4s per B row
#pragma unroll
    for (int i = 0; i < BITERS; i++) {
        int idx = tid + i * 256;
        int kk = idx / NQ, n4 = (idx % NQ) << 2;
        CP16(bs_base + (uint32_t)((kk * BSTR + n4) * 4), Bg + (size_t)kk * N + n4);
    }
    CP_COMMIT();
}

template<int MODE, int TBN>
__global__ void __launch_bounds__(256)
gemm_tc(const float* __restrict__ A, const float* __restrict__ B,
        float* __restrict__ Cc, const float* __restrict__ bias,
        int K, int N) {
    constexpr int BSTR = TBN + 8;
    constexpr int BSZ  = BK * BSTR;
    constexpr int NT   = TBN / 32;     // n-tiles per warp (4 or 8)
    constexpr int WN   = TBN / 4;      // warp n-width (32 or 64)

    extern __shared__ float sm[];
    uint32_t sm_u32 = (uint32_t)__cvta_generic_to_shared(sm);
    uint32_t as_b[2] = { sm_u32, sm_u32 + AS_SZ * 4 };
    uint32_t bs_b[2] = { sm_u32 + 2 * AS_SZ * 4, sm_u32 + (2 * AS_SZ + BSZ) * 4 };
    const uint32_t* Asm[2] = { (const uint32_t*)sm, (const uint32_t*)(sm + AS_SZ) };
    const uint32_t* Bsm[2] = { (const uint32_t*)(sm + 2 * AS_SZ), (const uint32_t*)(sm + 2 * AS_SZ + BSZ) };

    int tid  = threadIdx.x;
    int brow = blockIdx.y * BM;
    int bcol = blockIdx.x * TBN;
    int warp = tid >> 5, lane = tid & 31;
    int wm = (warp & 1) * 64, wn = (warp >> 1) * WN;
    int gid = lane >> 2, tg = lane & 3;

    float acc[4][NT][4];
#pragma unroll
    for (int i = 0; i < 4; i++)
#pragma unroll
        for (int j = 0; j < NT; j++)
#pragma unroll
            for (int r = 0; r < 4; r++) acc[i][j][r] = 0.f;

    const float* Abase = A + (size_t)brow * K;
    const float* Bbase = B + bcol;

    int nk = K / BK;
    cp_tile<TBN>(as_b[0], bs_b[0], Abase, Bbase, K, N, tid);

    for (int kt = 0; kt < nk; kt++) {
        int s = kt & 1;
        if (kt + 1 < nk) {
            cp_tile<TBN>(as_b[s ^ 1], bs_b[s ^ 1], Abase + (kt + 1) * BK,
                         Bbase + (size_t)(kt + 1) * BK * N, K, N, tid);
            asm volatile("cp.async.wait_group 1;\n" ::: "memory");
        } else {
            asm volatile("cp.async.wait_group 0;\n" ::: "memory");
        }
        __syncthreads();

        const uint32_t* as = Asm[s];
        const uint32_t* bs = Bsm[s];
#pragma unroll
        for (int ks = 0; ks < 4; ks++) {
            int k8 = ks * 8;
            uint32_t af[4][4], bf[NT][2];
#pragma unroll
            for (int mt = 0; mt < 4; mt++) {
                const uint32_t* ap = as + (wm + mt * 16 + gid) * AS_STRIDE + k8 + tg;
                af[mt][0] = ap[0];
                af[mt][2] = ap[4];
                af[mt][1] = ap[8 * AS_STRIDE];
                af[mt][3] = ap[8 * AS_STRIDE + 4];
            }
#pragma unroll
            for (int nt = 0; nt < NT; nt++) {
                const uint32_t* bp = bs + (k8 + tg) * BSTR + wn + nt * 8 + gid;
                bf[nt][0] = bp[0];
                bf[nt][1] = bp[4 * BSTR];
            }
#pragma unroll
            for (int mt = 0; mt < 4; mt++)
#pragma unroll
                for (int nt = 0; nt < NT; nt++)
                    mma_tf32(acc[mt][nt], af[mt], bf[nt]);
        }
        __syncthreads();
    }

    // epilogue
#pragma unroll
    for (int mt = 0; mt < 4; mt++) {
        int r0 = brow + wm + mt * 16 + gid;
#pragma unroll
        for (int nt = 0; nt < NT; nt++) {
            int c0 = bcol + wn + nt * 8 + tg * 2;
            float b0v = bias ? bias[c0] : 0.f;
            float b1v = bias ? bias[c0 + 1] : 0.f;
            float* p0 = Cc + (size_t)r0 * N + c0;
            float* p1 = Cc + (size_t)(r0 + 8) * N + c0;
            float v0 = acc[mt][nt][0] + b0v, v1 = acc[mt][nt][1] + b1v;
            float v2 = acc[mt][nt][2] + b0v, v3 = acc[mt][nt][3] + b1v;
            if (MODE == MODE_ADD) { v0 += p0[0]; v1 += p0[1]; v2 += p1[0]; v3 += p1[1]; }
            if (MODE == MODE_RELU_ROUND) {
                v0 = fmaxf(v0, 0.f); v1 = fmaxf(v1, 0.f); v2 = fmaxf(v2, 0.f); v3 = fmaxf(v3, 0.f);
            }
            if (MODE == MODE_ROUND || MODE == MODE_RELU_ROUND) {
                v0 = roundtf(v0); v1 = roundtf(v1); v2 = roundtf(v2); v3 = roundtf(v3);
            }
            p0[0] = v0; p0[1] = v1; p1[0] = v2; p1[1] = v3;
        }
    }
}

// ----------------------------------------------------------------------------
// Flash attention (unchanged from round 3)
// ----------------------------------------------------------------------------
__global__ void __launch_bounds__(128) attn_flash() {
    extern __shared__ float asm_[];
    float (*Qs)[ALD] = (float(*)[ALD])asm_;
    float (*Ks)[ALD] = (float(*)[ALD])(asm_ + 64 * ALD);
    float (*Vs)[ALD] = (float(*)[ALD])(asm_ + 2 * 64 * ALD);

    int qi = blockIdx.x, h = blockIdx.y, b = blockIdx.z;
    int q0 = qi * 64;
    int tid = threadIdx.x, lane = tid & 31, w = tid >> 5;
    int gid = lane >> 2, tg = lane & 3;
    size_t base = (size_t)(b * T_) * (3 * C_);
    int hoff = h * HS_;

    for (int i = tid; i < 64 * 16; i += 128) {
        int r = i >> 4, c4 = (i & 15) << 2;
        *(float4*)&Qs[r][c4] = *(const float4*)&g_qkv[base + (size_t)(q0 + r) * 3 * C_ + hoff + c4];
    }
    __syncthreads();

    uint32_t qf[8][4];
#pragma unroll
    for (int ks = 0; ks < 8; ks++) {
        const float* ap = &Qs[w * 16 + gid][ks * 8 + tg];
        qf[ks][0] = __float_as_uint(ap[0]);
        qf[ks][1] = __float_as_uint(ap[8 * ALD]);
        qf[ks][2] = __float_as_uint(ap[4]);
        qf[ks][3] = __float_as_uint(ap[8 * ALD + 4]);
    }

    float m0 = -1e30f, m1 = -1e30f, l0 = 0.f, l1 = 0.f;
    float acc_o[8][4];
#pragma unroll
    for (int nt = 0; nt < 8; nt++)
#pragma unroll
        for (int r = 0; r < 4; r++) acc_o[nt][r] = 0.f;

    int row0 = q0 + w * 16 + gid;
    int row1 = row0 + 8;
    float (*Pw)[ALD] = (float(*)[ALD])(asm_ + (size_t)w * 16 * ALD);

    for (int j0 = 0; j0 <= q0; j0 += 64) {
        __syncthreads();
        for (int i = tid; i < 64 * 16; i += 128) {
            int r = i >> 4, c4 = (i & 15) << 2;
            size_t rb = base + (size_t)(j0 + r) * 3 * C_ + hoff + c4;
            *(float4*)&Ks[r][c4] = *(const float4*)&g_qkv[rb + C_];
            *(float4*)&Vs[r][c4] = *(const float4*)&g_qkv[rb + 2 * C_];
        }
        __syncthreads();

        float sc[8][4];
#pragma unroll
        for (int nt = 0; nt < 8; nt++)
#pragma unroll
            for (int r = 0; r < 4; r++) sc[nt][r] = 0.f;
#pragma unroll
        for (int ks = 0; ks < 8; ks++) {
#pragma unroll
            for (int nt = 0; nt < 8; nt++) {
                uint32_t bf[2];
                bf[0] = __float_as_uint(Ks[nt * 8 + gid][ks * 8 + tg]);
                bf[1] = __float_as_uint(Ks[nt * 8 + gid][ks * 8 + tg + 4]);
                mma_tf32(sc[nt], qf[ks], bf);
            }
        }

        bool diag = (j0 == q0);
#pragma unroll
        for (int nt = 0; nt < 8; nt++) {
            sc[nt][0] *= SCALE_; sc[nt][1] *= SCALE_;
            sc[nt][2] *= SCALE_; sc[nt][3] *= SCALE_;
            if (diag) {
                int jg = j0 + nt * 8 + tg * 2;
                if (jg > row0)     sc[nt][0] = -1e30f;
                if (jg + 1 > row0) sc[nt][1] = -1e30f;
                if (jg > row1)     sc[nt][2] = -1e30f;
                if (jg + 1 > row1) sc[nt][3] = -1e30f;
            }
        }

        float mx0 = -1e30f, mx1 = -1e30f;
#pragma unroll
        for (int nt = 0; nt < 8; nt++) {
            mx0 = fmaxf(mx0, fmaxf(sc[nt][0], sc[nt][1]));
            mx1 = fmaxf(mx1, fmaxf(sc[nt][2], sc[nt][3]));
        }
        mx0 = fmaxf(mx0, __shfl_xor_sync(0xffffffffu, mx0, 1));
        mx0 = fmaxf(mx0, __shfl_xor_sync(0xffffffffu, mx0, 2));
        mx1 = fmaxf(mx1, __shfl_xor_sync(0xffffffffu, mx1, 1));
        mx1 = fmaxf(mx1, __shfl_xor_sync(0xffffffffu, mx1, 2));

        float mn0 = fmaxf(m0, mx0), mn1 = fmaxf(m1, mx1);
        float a0 = __expf(m0 - mn0), a1 = __expf(m1 - mn1);
        m0 = mn0; m1 = mn1;

        float s0 = 0.f, s1 = 0.f;
#pragma unroll
        for (int nt = 0; nt < 8; nt++) {
            float p0 = __expf(sc[nt][0] - mn0), p1 = __expf(sc[nt][1] - mn0);
            float p2 = __expf(sc[nt][2] - mn1), p3 = __expf(sc[nt][3] - mn1);
            s0 += p0 + p1; s1 += p2 + p3;
            Pw[gid][nt * 8 + 2 * tg]     = roundtf(p0);
            Pw[gid][nt * 8 + 2 * tg + 1] = roundtf(p1);
            Pw[gid + 8][nt * 8 + 2 * tg]     = roundtf(p2);
            Pw[gid + 8][nt * 8 + 2 * tg + 1] = roundtf(p3);
        }
        s0 += __shfl_xor_sync(0xffffffffu, s0, 1);
        s0 += __shfl_xor_sync(0xffffffffu, s0, 2);
        s1 += __shfl_xor_sync(0xffffffffu, s1, 1);
        s1 += __shfl_xor_sync(0xffffffffu, s1, 2);
        l0 = l0 * a0 + s0;
        l1 = l1 * a1 + s1;

#pragma unroll
        for (int nt = 0; nt < 8; nt++) {
            acc_o[nt][0] *= a0; acc_o[nt][1] *= a0;
            acc_o[nt][2] *= a1; acc_o[nt][3] *= a1;
        }
        __syncwarp();

#pragma unroll
        for (int ks = 0; ks < 8; ks++) {
            uint32_t af[4];
            const float* pp = &Pw[gid][ks * 8 + tg];
            af[0] = __float_as_uint(pp[0]);
            af[1] = __float_as_uint(pp[8 * ALD]);
            af[2] = __float_as_uint(pp[4]);
            af[3] = __float_as_uint(pp[8 * ALD + 4]);
#pragma unroll
            for (int nt = 0; nt < 8; nt++) {
                uint32_t bf[2];
                bf[0] = __float_as_uint(Vs[ks * 8 + tg][nt * 8 + gid]);
                bf[1] = __float_as_uint(Vs[ks * 8 + tg + 4][nt * 8 + gid]);
                mma_tf32(acc_o[nt], af, bf);
            }
        }
        __syncwarp();
    }

    float i0 = 1.f / l0, i1 = 1.f / l1;
#pragma unroll
    for (int nt = 0; nt < 8; nt++) {
        float2 v0 = make_float2(roundtf(acc_o[nt][0] * i0), roundtf(acc_o[nt][1] * i0));
        float2 v1 = make_float2(roundtf(acc_o[nt][2] * i1), roundtf(acc_o[nt][3] * i1));
        *(float2*)&g_o[(size_t)(b * T_ + row0) * C_ + hoff + nt * 8 + 2 * tg] = v0;
        *(float2*)&g_o[(size_t)(b * T_ + row1) * C_ + hoff + nt * 8 + 2 * tg] = v1;
    }
}

// ----------------------------------------------------------------------------
// Loss (float4)
// ----------------------------------------------------------------------------
__global__ void rowloss_k(const float* __restrict__ logits, const int* __restrict__ tgt) {
    __shared__ float red[256];
    int row = blockIdx.x;
    int tid = threadIdx.x;
    const float* L = logits + (size_t)row * V_;
    const float4* L4 = (const float4*)L;

    float mx = -3.4e38f;
    for (int j = tid; j < V_ / 4; j += 256) {
        float4 v = L4[j];
        mx = fmaxf(mx, fmaxf(fmaxf(v.x, v.y), fmaxf(v.z, v.w)));
    }
    red[tid] = mx; __syncthreads();
    for (int st = 128; st > 0; st >>= 1) { if (tid < st) red[tid] = fmaxf(red[tid], red[tid + st]); __syncthreads(); }
    mx = red[0]; __syncthreads();

    float s = 0.f;
    for (int j = tid; j < V_ / 4; j += 256) {
        float4 v = L4[j];
        s += __expf(v.x - mx) + __expf(v.y - mx) + __expf(v.z - mx) + __expf(v.w - mx);
    }
    red[tid] = s; __syncthreads();
    for (int st = 128; st > 0; st >>= 1) { if (tid < st) red[tid] += red[tid + st]; __syncthreads(); }
    if (tid == 0)
        g_rowloss[row] = -(L[tgt[row]] - mx - logf(red[0]));
}

__global__ void finloss_k(float* __restrict__ out) {
    __shared__ float red[256];
    int tid = threadIdx.x;
    float s = 0.f;
    for (int j = tid; j < M_; j += 256) s += g_rowloss[j];
    red[tid] = s; __syncthreads();
    for (int st = 128; st > 0; st >>= 1) { if (tid < st) red[tid] += red[tid + st]; __syncthreads(); }
    if (tid == 0) out[0] = red[0] * (1.f / M_);
}

// ----------------------------------------------------------------------------
// Host driver
// ----------------------------------------------------------------------------
extern "C" void kernel_launch(void* const* d_in, const int* in_sizes, int n_in,
                              void* d_out, int out_size) {
    const float* tok_emb = (const float*)d_in[0];
    const float* pos_emb = (const float*)d_in[1];
    const float* wq      = (const float*)d_in[2];
    const float* wk      = (const float*)d_in[3];
    const float* wv      = (const float*)d_in[4];
    const float* wproj   = (const float*)d_in[5];
    const float* bproj   = (const float*)d_in[6];
    const float* g1      = (const float*)d_in[7];
    const float* b1      = (const float*)d_in[8];
    const float* g2      = (const float*)d_in[9];
    const float* b2      = (const float*)d_in[10];
    const float* wf1     = (const float*)d_in[11];
    const float* bf1     = (const float*)d_in[12];
    const float* wf2     = (const float*)d_in[13];
    const float* bf2     = (const float*)d_in[14];
    const float* gf      = (const float*)d_in[15];
    const float* bf      = (const float*)d_in[16];
    const float* wlm     = (const float*)d_in[17];
    const float* blm     = (const float*)d_in[18];
    const int*   sources = (const int*)d_in[19];
    const int*   targets = (const int*)d_in[20];

    float* out = (float*)d_out;
    const size_t n_logits = (size_t)M_ * V_;

    float *px, *ph, *pqkv, *po, *pwqkv, *pff, *pwproj, *pwf1, *pwf2, *pwlm;
    cudaGetSymbolAddress((void**)&px,     g_x);
    cudaGetSymbolAddress((void**)&ph,     g_h);
    cudaGetSymbolAddress((void**)&pqkv,   g_qkv);
    cudaGetSymbolAddress((void**)&po,     g_o);
    cudaGetSymbolAddress((void**)&pwqkv,  g_wqkv);
    cudaGetSymbolAddress((void**)&pff,    g_ff);
    cudaGetSymbolAddress((void**)&pwproj, g_wproj);
    cudaGetSymbolAddress((void**)&pwf1,   g_wf1);
    cudaGetSymbolAddress((void**)&pwf2,   g_wf2);
    cudaGetSymbolAddress((void**)&pwlm,   g_wlm);

    const int SMEM_N = 2 * (AS_SZ + BK * (128 + 8)) * 4;   // 71680 (TBN=128)
    const int SMEM_W = 2 * (AS_SZ + BK * (256 + 8)) * 4;   // 104448 (TBN=256)

    cudaFuncSetAttribute(gemm_tc<MODE_ADD, 128>,        cudaFuncAttributeMaxDynamicSharedMemorySize, SMEM_N);
    cudaFuncSetAttribute(gemm_tc<MODE_PLAIN, 256>,      cudaFuncAttributeMaxDynamicSharedMemorySize, SMEM_W);
    cudaFuncSetAttribute(gemm_tc<MODE_ROUND, 256>,      cudaFuncAttributeMaxDynamicSharedMemorySize, SMEM_W);
    cudaFuncSetAttribute(gemm_tc<MODE_RELU_ROUND, 256>, cudaFuncAttributeMaxDynamicSharedMemorySize, SMEM_W);
    cudaFuncSetAttribute(attn_flash, cudaFuncAttributeMaxDynamicSharedMemorySize, ATT_SMEM);

    // 0. pre-round weights
    {
        size_t n4;
        n4 = (size_t)NB_ * C_ * C_ / 4;
        round_w_k<<<(unsigned)((n4 + 255) / 256), 256>>>((const float4*)wproj, (float4*)pwproj, n4);
        n4 = (size_t)NB_ * C_ * FF_ / 4;
        round_w_k<<<(unsigned)((n4 + 255) / 256), 256>>>((const float4*)wf1, (float4*)pwf1, n4);
        round_w_k<<<(unsigned)((n4 + 255) / 256), 256>>>((const float4*)wf2, (float4*)pwf2, n4);
        n4 = (size_t)C_ * V_ / 4;
        round_w_k<<<(unsigned)((n4 + 255) / 256), 256>>>((const float4*)wlm, (float4*)pwlm, n4);
    }

    // 1. embedding
    embed_k<<<(M_ * 192) / 256, 256>>>((const float4*)tok_emb, (const float4*)pos_emb, sources);

    // 2. transformer blocks
    for (int i = 0; i < NB_; i++) {
        const float* wq_i = wq + (size_t)i * H_ * C_ * HS_;
        const float* wk_i = wk + (size_t)i * H_ * C_ * HS_;
        const float* wv_i = wv + (size_t)i * H_ * C_ * HS_;

        ln_k<<<M_ / 8, 256>>>(px, ph, g1 + i * C_, b1 + i * C_);
        pack_qkv_k<<<(C_ * 3 * C_ + 255) / 256, 256>>>(wq_i, wk_i, wv_i);

        gemm_tc<MODE_ROUND, 256><<<dim3((3 * C_) / 256, M_ / BM), 256, SMEM_W>>>(
            ph, pwqkv, pqkv, nullptr, C_, 3 * C_);

        attn_flash<<<dim3(T_ / 64, H_, B_), 128, ATT_SMEM>>>();

        gemm_tc<MODE_ADD, 128><<<dim3(C_ / 128, M_ / BM), 256, SMEM_N>>>(
            po, pwproj + (size_t)i * C_ * C_, px, bproj + i * C_, C_, C_);

        ln_k<<<M_ / 8, 256>>>(px, ph, g2 + i * C_, b2 + i * C_);

        gemm_tc<MODE_RELU_ROUND, 256><<<dim3(FF_ / 256, M_ / BM), 256, SMEM_W>>>(
            ph, pwf1 + (size_t)i * C_ * FF_, pff, bf1 + i * FF_, C_, FF_);

        gemm_tc<MODE_ADD, 128><<<dim3(C_ / 128, M_ / BM), 256, SMEM_N>>>(
            pff, pwf2 + (size_t)i * FF_ * C_, px, bf2 + i * C_, FF_, C_);
    }

    // 3. final LN + LM head
    ln_k<<<M_ / 8, 256>>>(px, ph, gf, bf);
    gemm_tc<MODE_PLAIN, 256><<<dim3(V_ / 256, M_ / BM), 256, SMEM_W>>>(
        ph, pwlm, out, blm, C_, V_);

    // 4. loss
    rowloss_k<<<M_, 256>>>(out, targets);
    if ((size_t)out_size > n_logits)
        finloss_k<<<1, 256>>>(out + n_logits);
}

// round 8
// speedup vs baseline: 7.5287x; 1.9296x over previous
#include <cuda_runtime.h>
#include <cuda_fp16.h>
#include <cstdint>
#include <math.h>

// Problem constants
#define V_   32000
#define C_   768
#define T_   1024
#define H_   12
#define HS_  64
#define FF_  9216
#define NB_  3
#define B_   4
#define M_   (B_ * T_)
#define EPS_ 1e-5f
#define SCALE_ 0.03608439182435161f   // 768^-0.5

// FP16 GEMM tiling: CTA 128x128x32, 8 warps of 64x32
#define AH_STR 40                       // halves (80B rows: ldmatrix conflict-free)
#define BH_STR 136                      // halves (272B rows)
#define AH_SZ  (128 * AH_STR)           // 5120 halves
#define BH_SZ  (32 * BH_STR)            // 4352 halves
#define GH_SMEM (2 * (AH_SZ + BH_SZ) * 2)   // 37888 bytes

// Attention tiling
#define ALD 68
#define ATT_SMEM (3 * 64 * ALD * 4)

// Epilogue modes
#define MODE_PLAIN 0     // float out
#define MODE_ROUND 1     // float out, fp16-rounded values
#define MODE_ADD 2       // float out += residual
#define MODE_RELU 3      // half out, relu

// ----------------------------------------------------------------------------
// Scratch
// ----------------------------------------------------------------------------
__device__ float  g_x[M_ * C_];
__device__ __half g_h[M_ * C_];
__device__ float  g_qkv[M_ * 3 * C_];
__device__ __half g_o[M_ * C_];
__device__ __half g_wqkv[C_ * 3 * C_];              // [K=768, N=2304]
__device__ __half g_wproj[NB_ * C_ * C_];
__device__ __half g_wf1[(size_t)NB_ * C_ * FF_];
__device__ __half g_wf2[(size_t)NB_ * FF_ * C_];
__device__ __half g_wlm[(size_t)C_ * V_];
__device__ __half g_ff[(size_t)M_ * FF_];
__device__ float  g_rowloss[M_];

// ----------------------------------------------------------------------------
// PTX helpers
// ----------------------------------------------------------------------------
#define CP16(dst, src) asm volatile("cp.async.cg.shared.global [%0], [%1], 16;\n" :: "r"(dst), "l"(src) : "memory")
#define CP_COMMIT() asm volatile("cp.async.commit_group;\n" ::: "memory")

__device__ __forceinline__ uint32_t f2tf32(float v) {
    uint32_t r; asm("cvt.rna.tf32.f32 %0, %1;" : "=r"(r) : "f"(v)); return r;
}
__device__ __forceinline__ float roundtf(float v) {
    return __uint_as_float(f2tf32(v));
}
__device__ __forceinline__ float roundh(float v) {
    return __half2float(__float2half_rn(v));
}

__device__ __forceinline__ void mma_tf32(float* c, const uint32_t* a, const uint32_t* b) {
    asm volatile("mma.sync.aligned.m16n8k8.row.col.f32.tf32.tf32.f32 "
                 "{%0,%1,%2,%3}, {%4,%5,%6,%7}, {%8,%9}, {%0,%1,%2,%3};"
                 : "+f"(c[0]), "+f"(c[1]), "+f"(c[2]), "+f"(c[3])
                 : "r"(a[0]), "r"(a[1]), "r"(a[2]), "r"(a[3]), "r"(b[0]), "r"(b[1]));
}

__device__ __forceinline__ void mma_f16(float* c, const uint32_t* a, uint32_t b0, uint32_t b1) {
    asm volatile("mma.sync.aligned.m16n8k16.row.col.f32.f16.f16.f32 "
                 "{%0,%1,%2,%3}, {%4,%5,%6,%7}, {%8,%9}, {%0,%1,%2,%3};"
                 : "+f"(c[0]), "+f"(c[1]), "+f"(c[2]), "+f"(c[3])
                 : "r"(a[0]), "r"(a[1]), "r"(a[2]), "r"(a[3]), "r"(b0), "r"(b1));
}

#define LDSM_X4(r, addr) \
    asm volatile("ldmatrix.sync.aligned.m8n8.x4.shared.b16 {%0,%1,%2,%3}, [%4];" \
                 : "=r"((r)[0]), "=r"((r)[1]), "=r"((r)[2]), "=r"((r)[3]) : "r"(addr))
#define LDSM_X4_T(r, addr) \
    asm volatile("ldmatrix.sync.aligned.m8n8.x4.trans.shared.b16 {%0,%1,%2,%3}, [%4];" \
                 : "=r"((r)[0]), "=r"((r)[1]), "=r"((r)[2]), "=r"((r)[3]) : "r"(addr))

// ----------------------------------------------------------------------------
// Weight convert: fp32 -> fp16 (vectorized)
// ----------------------------------------------------------------------------
__global__ void tohalf_k(const float4* __restrict__ in, uint2* __restrict__ out, size_t n4) {
    size_t i = (size_t)blockIdx.x * blockDim.x + threadIdx.x;
    if (i < n4) {
        float4 v = in[i];
        __half2 h0 = __floats2half2_rn(v.x, v.y);
        __half2 h1 = __floats2half2_rn(v.z, v.w);
        out[i] = make_uint2(*(uint32_t*)&h0, *(uint32_t*)&h1);
    }
}

// ----------------------------------------------------------------------------
// Embedding (float4)
// ----------------------------------------------------------------------------
__global__ void embed_k(const float4* __restrict__ tok, const float4* __restrict__ pos,
                        const int* __restrict__ src) {
    int idx = blockIdx.x * blockDim.x + threadIdx.x;
    int row = idx / 192;
    int c4  = idx - row * 192;
    int t   = row % T_;
    float4 a = tok[(size_t)src[row] * 192 + c4];
    float4 p = pos[t * 192 + c4];
    ((float4*)g_x)[idx] = make_float4(a.x + p.x, a.y + p.y, a.z + p.z, a.w + p.w);
}

// ----------------------------------------------------------------------------
// LayerNorm: warp per row, fp16 output
// ----------------------------------------------------------------------------
__global__ void __launch_bounds__(256) ln_k(const float* __restrict__ in, __half* __restrict__ out,
                                            const float* __restrict__ g, const float* __restrict__ b) {
    int warp = threadIdx.x >> 5, lane = threadIdx.x & 31;
    int row = blockIdx.x * 8 + warp;
    const float4* x4 = (const float4*)(in + (size_t)row * C_);

    float4 v[6];
    float s = 0.f, s2 = 0.f;
#pragma unroll
    for (int i = 0; i < 6; i++) {
        v[i] = x4[lane + 32 * i];
        s  += v[i].x + v[i].y + v[i].z + v[i].w;
        s2 += v[i].x * v[i].x + v[i].y * v[i].y + v[i].z * v[i].z + v[i].w * v[i].w;
    }
#pragma unroll
    for (int o = 16; o > 0; o >>= 1) {
        s  += __shfl_xor_sync(0xffffffffu, s, o);
        s2 += __shfl_xor_sync(0xffffffffu, s2, o);
    }
    float mean = s * (1.f / C_);
    float var  = s2 * (1.f / C_) - mean * mean;
    float inv  = rsqrtf(var + EPS_);

    const float4* g4 = (const float4*)g;
    const float4* b4 = (const float4*)b;
    uint2* o4 = (uint2*)(out + (size_t)row * C_);
#pragma unroll
    for (int i = 0; i < 6; i++) {
        float4 gg = g4[lane + 32 * i], bb = b4[lane + 32 * i];
        __half2 h0 = __floats2half2_rn((v[i].x - mean) * inv * gg.x + bb.x,
                                       (v[i].y - mean) * inv * gg.y + bb.y);
        __half2 h1 = __floats2half2_rn((v[i].z - mean) * inv * gg.z + bb.z,
                                       (v[i].w - mean) * inv * gg.w + bb.w);
        o4[lane + 32 * i] = make_uint2(*(uint32_t*)&h0, *(uint32_t*)&h1);
    }
}

// ----------------------------------------------------------------------------
// Pack wq/wk/wv into [K=768][N=2304] fp16
// ----------------------------------------------------------------------------
__global__ void pack_qkv_k(const float* __restrict__ wq, const float* __restrict__ wk,
                           const float* __restrict__ wv) {
    int idx = blockIdx.x * blockDim.x + threadIdx.x;   // C_*3C_
    if (idx >= C_ * 3 * C_) return;
    int c   = idx / (3 * C_);
    int col = idx - c * (3 * C_);
    const float* w = (col < C_) ? wq : (col < 2 * C_ ? wk : wv);
    int j = col % C_;
    int h = j / HS_, d = j % HS_;
    g_wqkv[idx] = __float2half_rn(w[((size_t)h * C_ + c) * HS_ + d]);
}

// ----------------------------------------------------------------------------
// FP16 tensor-core GEMM: C[M,N] = A[M,K] @ B[K,N] (+bias/res/relu)
// CTA 128x128x32, 8 warps 64x32, mma.m16n8k16, ldmatrix, cp.async double buffer.
// ----------------------------------------------------------------------------
__device__ __forceinline__ void gh_load(uint32_t sa, uint32_t sb,
                                        const __half* Ag, const __half* Bg,
                                        int K, int N, int tid) {
#pragma unroll
    for (int i = 0; i < 2; i++) {
        int idx = tid + i * 256;
        int row = idx >> 2, q = idx & 3;           // A: 128 rows x 4 chunks
        CP16(sa + (uint32_t)((row * AH_STR + q * 8) * 2), Ag + (size_t)row * K + q * 8);
    }
#pragma unroll
    for (int i = 0; i < 2; i++) {
        int idx = tid + i * 256;
        int row = idx >> 4, q = idx & 15;          // B: 32 rows x 16 chunks
        CP16(sb + (uint32_t)((row * BH_STR + q * 8) * 2), Bg + (size_t)row * N + q * 8);
    }
    CP_COMMIT();
}

template<int MODE>
__global__ void __launch_bounds__(256)
gemm_h(const __half* __restrict__ A, const __half* __restrict__ B,
       void* __restrict__ Cv, const float* __restrict__ bias,
       int K, int N) {
    extern __shared__ __half hs[];
    uint32_t s_u = (uint32_t)__cvta_generic_to_shared(hs);
    uint32_t a_b[2] = { s_u, s_u + AH_SZ * 2 };
    uint32_t b_b[2] = { s_u + 2 * AH_SZ * 2, s_u + (2 * AH_SZ + BH_SZ) * 2 };

    int tid  = threadIdx.x;
    int warp = tid >> 5, lane = tid & 31;
    int brow = blockIdx.x * 128;
    int bcol = blockIdx.y * 128;
    int wm = (warp & 1) * 64, wn = (warp >> 1) * 32;
    int gid = lane >> 2, tg = lane & 3;
    int l16 = lane & 15, lh = lane >> 4;

    float acc[4][4][4];
#pragma unroll
    for (int i = 0; i < 4; i++)
#pragma unroll
        for (int j = 0; j < 4; j++)
#pragma unroll
            for (int r = 0; r < 4; r++) acc[i][j][r] = 0.f;

    const __half* Abase = A + (size_t)brow * K;
    const __half* Bbase = B + bcol;

    int nk = K / 32;
    gh_load(a_b[0], b_b[0], Abase, Bbase, K, N, tid);

    for (int kt = 0; kt < nk; kt++) {
        int s = kt & 1;
        if (kt + 1 < nk) {
            gh_load(a_b[s ^ 1], b_b[s ^ 1], Abase + (kt + 1) * 32,
                    Bbase + (size_t)(kt + 1) * 32 * N, K, N, tid);
            asm volatile("cp.async.wait_group 1;\n" ::: "memory");
        } else {
            asm volatile("cp.async.wait_group 0;\n" ::: "memory");
        }
        __syncthreads();

#pragma unroll
        for (int ks = 0; ks < 2; ks++) {
            uint32_t af[4][4], bfr[2][4];
#pragma unroll
            for (int mt = 0; mt < 4; mt++) {
                uint32_t addr = a_b[s] + (uint32_t)(((wm + mt * 16 + l16) * AH_STR
                                                    + ks * 16 + lh * 8) * 2);
                LDSM_X4(af[mt], addr);
            }
#pragma unroll
            for (int np = 0; np < 2; np++) {
                uint32_t addr = b_b[s] + (uint32_t)(((ks * 16 + l16) * BH_STR
                                                    + wn + np * 16 + lh * 8) * 2);
                LDSM_X4_T(bfr[np], addr);
            }
#pragma unroll
            for (int mt = 0; mt < 4; mt++)
#pragma unroll
                for (int nt = 0; nt < 4; nt++)
                    mma_f16(acc[mt][nt], af[mt], bfr[nt >> 1][(nt & 1) * 2],
                            bfr[nt >> 1][(nt & 1) * 2 + 1]);
        }
        __syncthreads();
    }

    // epilogue
#pragma unroll
    for (int mt = 0; mt < 4; mt++) {
        int r0 = brow + wm + mt * 16 + gid;
#pragma unroll
        for (int nt = 0; nt < 4; nt++) {
            int c0 = bcol + wn + nt * 8 + tg * 2;
            float b0v = bias ? bias[c0] : 0.f;
            float b1v = bias ? bias[c0 + 1] : 0.f;
            float v0 = acc[mt][nt][0] + b0v, v1 = acc[mt][nt][1] + b1v;
            float v2 = acc[mt][nt][2] + b0v, v3 = acc[mt][nt][3] + b1v;
            if (MODE == MODE_RELU) {
                __half* ph = (__half*)Cv;
                __half2 h0 = __floats2half2_rn(fmaxf(v0, 0.f), fmaxf(v1, 0.f));
                __half2 h1 = __floats2half2_rn(fmaxf(v2, 0.f), fmaxf(v3, 0.f));
                *(__half2*)(ph + (size_t)r0 * N + c0) = h0;
                *(__half2*)(ph + (size_t)(r0 + 8) * N + c0) = h1;
            } else {
                float* pf = (float*)Cv;
                float* p0 = pf + (size_t)r0 * N + c0;
                float* p1 = pf + (size_t)(r0 + 8) * N + c0;
                if (MODE == MODE_ADD) { v0 += p0[0]; v1 += p0[1]; v2 += p1[0]; v3 += p1[1]; }
                if (MODE == MODE_ROUND) {
                    v0 = roundh(v0); v1 = roundh(v1); v2 = roundh(v2); v3 = roundh(v3);
                }
                p0[0] = v0; p0[1] = v1; p1[0] = v2; p1[1] = v3;
            }
        }
    }
}

// ----------------------------------------------------------------------------
// Flash attention (tf32 mma; reads fp32 g_qkv, writes fp16 g_o)
// ----------------------------------------------------------------------------
__global__ void __launch_bounds__(128) attn_flash() {
    extern __shared__ float asm_[];
    float (*Qs)[ALD] = (float(*)[ALD])asm_;
    float (*Ks)[ALD] = (float(*)[ALD])(asm_ + 64 * ALD);
    float (*Vs)[ALD] = (float(*)[ALD])(asm_ + 2 * 64 * ALD);

    int qi = blockIdx.x, h = blockIdx.y, b = blockIdx.z;
    int q0 = qi * 64;
    int tid = threadIdx.x, lane = tid & 31, w = tid >> 5;
    int gid = lane >> 2, tg = lane & 3;
    size_t base = (size_t)(b * T_) * (3 * C_);
    int hoff = h * HS_;

    for (int i = tid; i < 64 * 16; i += 128) {
        int r = i >> 4, c4 = (i & 15) << 2;
        *(float4*)&Qs[r][c4] = *(const float4*)&g_qkv[base + (size_t)(q0 + r) * 3 * C_ + hoff + c4];
    }
    __syncthreads();

    uint32_t qf[8][4];
#pragma unroll
    for (int ks = 0; ks < 8; ks++) {
        const float* ap = &Qs[w * 16 + gid][ks * 8 + tg];
        qf[ks][0] = __float_as_uint(ap[0]);
        qf[ks][1] = __float_as_uint(ap[8 * ALD]);
        qf[ks][2] = __float_as_uint(ap[4]);
        qf[ks][3] = __float_as_uint(ap[8 * ALD + 4]);
    }

    float m0 = -1e30f, m1 = -1e30f, l0 = 0.f, l1 = 0.f;
    float acc_o[8][4];
#pragma unroll
    for (int nt = 0; nt < 8; nt++)
#pragma unroll
        for (int r = 0; r < 4; r++) acc_o[nt][r] = 0.f;

    int row0 = q0 + w * 16 + gid;
    int row1 = row0 + 8;
    float (*Pw)[ALD] = (float(*)[ALD])(asm_ + (size_t)w * 16 * ALD);

    for (int j0 = 0; j0 <= q0; j0 += 64) {
        __syncthreads();
        for (int i = tid; i < 64 * 16; i += 128) {
            int r = i >> 4, c4 = (i & 15) << 2;
            size_t rb = base + (size_t)(j0 + r) * 3 * C_ + hoff + c4;
            *(float4*)&Ks[r][c4] = *(const float4*)&g_qkv[rb + C_];
            *(float4*)&Vs[r][c4] = *(const float4*)&g_qkv[rb + 2 * C_];
        }
        __syncthreads();

        float sc[8][4];
#pragma unroll
        for (int nt = 0; nt < 8; nt++)
#pragma unroll
            for (int r = 0; r < 4; r++) sc[nt][r] = 0.f;
#pragma unroll
        for (int ks = 0; ks < 8; ks++) {
#pragma unroll
            for (int nt = 0; nt < 8; nt++) {
                uint32_t bf[2];
                bf[0] = __float_as_uint(Ks[nt * 8 + gid][ks * 8 + tg]);
                bf[1] = __float_as_uint(Ks[nt * 8 + gid][ks * 8 + tg + 4]);
                mma_tf32(sc[nt], qf[ks], bf);
            }
        }

        bool diag = (j0 == q0);
#pragma unroll
        for (int nt = 0; nt < 8; nt++) {
            sc[nt][0] *= SCALE_; sc[nt][1] *= SCALE_;
            sc[nt][2] *= SCALE_; sc[nt][3] *= SCALE_;
            if (diag) {
                int jg = j0 + nt * 8 + tg * 2;
                if (jg > row0)     sc[nt][0] = -1e30f;
                if (jg + 1 > row0) sc[nt][1] = -1e30f;
                if (jg > row1)     sc[nt][2] = -1e30f;
                if (jg + 1 > row1) sc[nt][3] = -1e30f;
            }
        }

        float mx0 = -1e30f, mx1 = -1e30f;
#pragma unroll
        for (int nt = 0; nt < 8; nt++) {
            mx0 = fmaxf(mx0, fmaxf(sc[nt][0], sc[nt][1]));
            mx1 = fmaxf(mx1, fmaxf(sc[nt][2], sc[nt][3]));
        }
        mx0 = fmaxf(mx0, __shfl_xor_sync(0xffffffffu, mx0, 1));
        mx0 = fmaxf(mx0, __shfl_xor_sync(0xffffffffu, mx0, 2));
        mx1 = fmaxf(mx1, __shfl_xor_sync(0xffffffffu, mx1, 1));
        mx1 = fmaxf(mx1, __shfl_xor_sync(0xffffffffu, mx1, 2));

        float mn0 = fmaxf(m0, mx0), mn1 = fmaxf(m1, mx1);
        float a0 = __expf(m0 - mn0), a1 = __expf(m1 - mn1);
        m0 = mn0; m1 = mn1;

        float s0 = 0.f, s1 = 0.f;
#pragma unroll
        for (int nt = 0; nt < 8; nt++) {
            float p0 = __expf(sc[nt][0] - mn0), p1 = __expf(sc[nt][1] - mn0);
            float p2 = __expf(sc[nt][2] - mn1), p3 = __expf(sc[nt][3] - mn1);
            s0 += p0 + p1; s1 += p2 + p3;
            Pw[gid][nt * 8 + 2 * tg]     = roundtf(p0);
            Pw[gid][nt * 8 + 2 * tg + 1] = roundtf(p1);
            Pw[gid + 8][nt * 8 + 2 * tg]     = roundtf(p2);
            Pw[gid + 8][nt * 8 + 2 * tg + 1] = roundtf(p3);
        }
        s0 += __shfl_xor_sync(0xffffffffu, s0, 1);
        s0 += __shfl_xor_sync(0xffffffffu, s0, 2);
        s1 += __shfl_xor_sync(0xffffffffu, s1, 1);
        s1 += __shfl_xor_sync(0xffffffffu, s1, 2);
        l0 = l0 * a0 + s0;
        l1 = l1 * a1 + s1;

#pragma unroll
        for (int nt = 0; nt < 8; nt++) {
            acc_o[nt][0] *= a0; acc_o[nt][1] *= a0;
            acc_o[nt][2] *= a1; acc_o[nt][3] *= a1;
        }
        __syncwarp();

#pragma unroll
        for (int ks = 0; ks < 8; ks++) {
            uint32_t af[4];
            const float* pp = &Pw[gid][ks * 8 + tg];
            af[0] = __float_as_uint(pp[0]);
            af[1] = __float_as_uint(pp[8 * ALD]);
            af[2] = __float_as_uint(pp[4]);
            af[3] = __float_as_uint(pp[8 * ALD + 4]);
#pragma unroll
            for (int nt = 0; nt < 8; nt++) {
                uint32_t bf[2];
                bf[0] = __float_as_uint(Vs[ks * 8 + tg][nt * 8 + gid]);
                bf[1] = __float_as_uint(Vs[ks * 8 + tg + 4][nt * 8 + gid]);
                mma_tf32(acc_o[nt], af, bf);
            }
        }
        __syncwarp();
    }

    float i0 = 1.f / l0, i1 = 1.f / l1;
#pragma unroll
    for (int nt = 0; nt < 8; nt++) {
        __half2 h0 = __floats2half2_rn(acc_o[nt][0] * i0, acc_o[nt][1] * i0);
        __half2 h1 = __floats2half2_rn(acc_o[nt][2] * i1, acc_o[nt][3] * i1);
        *(__half2*)&g_o[(size_t)(b * T_ + row0) * C_ + hoff + nt * 8 + 2 * tg] = h0;
        *(__half2*)&g_o[(size_t)(b * T_ + row1) * C_ + hoff + nt * 8 + 2 * tg] = h1;
    }
}

// ----------------------------------------------------------------------------
// Loss (float4)
// ----------------------------------------------------------------------------
__global__ void rowloss_k(const float* __restrict__ logits, const int* __restrict__ tgt) {
    __shared__ float red[256];
    int row = blockIdx.x;
    int tid = threadIdx.x;
    const float* L = logits + (size_t)row * V_;
    const float4* L4 = (const float4*)L;

    float mx = -3.4e38f;
    for (int j = tid; j < V_ / 4; j += 256) {
        float4 v = L4[j];
        mx = fmaxf(mx, fmaxf(fmaxf(v.x, v.y), fmaxf(v.z, v.w)));
    }
    red[tid] = mx; __syncthreads();
    for (int st = 128; st > 0; st >>= 1) { if (tid < st) red[tid] = fmaxf(red[tid], red[tid + st]); __syncthreads(); }
    mx = red[0]; __syncthreads();

    float s = 0.f;
    for (int j = tid; j < V_ / 4; j += 256) {
        float4 v = L4[j];
        s += __expf(v.x - mx) + __expf(v.y - mx) + __expf(v.z - mx) + __expf(v.w - mx);
    }
    red[tid] = s; __syncthreads();
    for (int st = 128; st > 0; st >>= 1) { if (tid < st) red[tid] += red[tid + st]; __syncthreads(); }
    if (tid == 0)
        g_rowloss[row] = -(L[tgt[row]] - mx - logf(red[0]));
}

__global__ void finloss_k(float* __restrict__ out) {
    __shared__ float red[256];
    int tid = threadIdx.x;
    float s = 0.f;
    for (int j = tid; j < M_; j += 256) s += g_rowloss[j];
    red[tid] = s; __syncthreads();
    for (int st = 128; st > 0; st >>= 1) { if (tid < st) red[tid] += red[tid + st]; __syncthreads(); }
    if (tid == 0) out[0] = red[0] * (1.f / M_);
}

// ----------------------------------------------------------------------------
// Host driver
// ----------------------------------------------------------------------------
extern "C" void kernel_launch(void* const* d_in, const int* in_sizes, int n_in,
                              void* d_out, int out_size) {
    const float* tok_emb = (const float*)d_in[0];
    const float* pos_emb = (const float*)d_in[1];
    const float* wq      = (const float*)d_in[2];
    const float* wk      = (const float*)d_in[3];
    const float* wv      = (const float*)d_in[4];
    const float* wproj   = (const float*)d_in[5];
    const float* bproj   = (const float*)d_in[6];
    const float* g1      = (const float*)d_in[7];
    const float* b1      = (const float*)d_in[8];
    const float* g2      = (const float*)d_in[9];
    const float* b2      = (const float*)d_in[10];
    const float* wf1     = (const float*)d_in[11];
    const float* bf1     = (const float*)d_in[12];
    const float* wf2     = (const float*)d_in[13];
    const float* bf2     = (const float*)d_in[14];
    const float* gf      = (const float*)d_in[15];
    const float* bf      = (const float*)d_in[16];
    const float* wlm     = (const float*)d_in[17];
    const float* blm     = (const float*)d_in[18];
    const int*   sources = (const int*)d_in[19];
    const int*   targets = (const int*)d_in[20];

    float* out = (float*)d_out;
    const size_t n_logits = (size_t)M_ * V_;

    float  *px, *pqkv;
    __half *ph, *po, *pwqkv, *pff, *pwproj, *pwf1, *pwf2, *pwlm;
    cudaGetSymbolAddress((void**)&px,     g_x);
    cudaGetSymbolAddress((void**)&ph,     g_h);
    cudaGetSymbolAddress((void**)&pqkv,   g_qkv);
    cudaGetSymbolAddress((void**)&po,     g_o);
    cudaGetSymbolAddress((void**)&pwqkv,  g_wqkv);
    cudaGetSymbolAddress((void**)&pff,    g_ff);
    cudaGetSymbolAddress((void**)&pwproj, g_wproj);
    cudaGetSymbolAddress((void**)&pwf1,   g_wf1);
    cudaGetSymbolAddress((void**)&pwf2,   g_wf2);
    cudaGetSymbolAddress((void**)&pwlm,   g_wlm);

    cudaFuncSetAttribute(attn_flash, cudaFuncAttributeMaxDynamicSharedMemorySize, ATT_SMEM);

    // 0. convert weights to fp16 (no transpose; B consumed as [K,N])
    {
        size_t n4;
        n4 = (size_t)NB_ * C_ * C_ / 4;
        tohalf_k<<<(unsigned)((n4 + 255) / 256), 256>>>((const float4*)wproj, (uint2*)pwproj, n4);
        n4 = (size_t)NB_ * C_ * FF_ / 4;
        tohalf_k<<<(unsigned)((n4 + 255) / 256), 256>>>((const float4*)wf1, (uint2*)pwf1, n4);
        tohalf_k<<<(unsigned)((n4 + 255) / 256), 256>>>((const float4*)wf2, (uint2*)pwf2, n4);
        n4 = (size_t)C_ * V_ / 4;
        tohalf_k<<<(unsigned)((n4 + 255) / 256), 256>>>((const float4*)wlm, (uint2*)pwlm, n4);
    }

    // 1. embedding
    embed_k<<<(M_ * 192) / 256, 256>>>((const float4*)tok_emb, (const float4*)pos_emb, sources);

    // 2. transformer blocks
    for (int i = 0; i < NB_; i++) {
        const float* wq_i = wq + (size_t)i * H_ * C_ * HS_;
        const float* wk_i = wk + (size_t)i * H_ * C_ * HS_;
        const float* wv_i = wv + (size_t)i * H_ * C_ * HS_;

        ln_k<<<M_ / 8, 256>>>(px, ph, g1 + i * C_, b1 + i * C_);
        pack_qkv_k<<<(C_ * 3 * C_ + 255) / 256, 256>>>(wq_i, wk_i, wv_i);

        // qkv = h @ Wqkv -> fp32 (fp16-rounded values)
        gemm_h<MODE_ROUND><<<dim3(M_ / 128, (3 * C_) / 128), 256, GH_SMEM>>>(
            ph, pwqkv, pqkv, nullptr, C_, 3 * C_);

        attn_flash<<<dim3(T_ / 64, H_, B_), 128, ATT_SMEM>>>();

        // x += o @ wproj + bproj
        gemm_h<MODE_ADD><<<dim3(M_ / 128, C_ / 128), 256, GH_SMEM>>>(
            po, pwproj + (size_t)i * C_ * C_, px, bproj + i * C_, C_, C_);

        ln_k<<<M_ / 8, 256>>>(px, ph, g2 + i * C_, b2 + i * C_);

        // ff = relu(h @ wf1 + bf1) -> fp16
        gemm_h<MODE_RELU><<<dim3(M_ / 128, FF_ / 128), 256, GH_SMEM>>>(
            ph, pwf1 + (size_t)i * C_ * FF_, pff, bf1 + i * FF_, C_, FF_);

        // x += ff @ wf2 + bf2
        gemm_h<MODE_ADD><<<dim3(M_ / 128, C_ / 128), 256, GH_SMEM>>>(
            pff, pwf2 + (size_t)i * FF_ * C_, px, bf2 + i * C_, FF_, C_);
    }

    // 3. final LN + LM head -> d_out
    ln_k<<<M_ / 8, 256>>>(px, ph, gf, bf);
    gemm_h<MODE_PLAIN><<<dim3(M_ / 128, V_ / 128), 256, GH_SMEM>>>(
        ph, pwlm, out, blm, C_, V_);

    // 4. loss
    rowloss_k<<<M_, 256>>>(out, targets);
    if ((size_t)out_size > n_logits)
        finloss_k<<<1, 256>>>(out + n_logits);
}